// round 1
// baseline (speedup 1.0000x reference)
#include <cuda_runtime.h>

#define NU 100000
#define NS 50000
#define NG 50
#define NW 20000
#define NT 10
#define CC 64
#define FF 384
#define E_US 1000000
#define E_GS 150000
#define E_WS 50000
#define E_TS 50000
#define E_LI 200000

// ---------------- scratch (device globals; allocation-free) ----------------
__device__ float g_xu[NU*CC];     // users features (phase0 out / layer2 out)
__device__ float g_xs[NS*CC];     // series features (phase0 out / layer2 out)
__device__ float g_yu[NU*CC];     // users layer1 out (relu'd -> layer2 in)
__device__ float g_ys[NS*CC];     // series layer1 out
__device__ float g_xg[NG*CC];     // genres layer1 out
__device__ float g_xw[NW*CC];     // writer layer1 out
__device__ float g_xt[NT*CC];     // type layer1 out
__device__ float g_aggU[NU*CC];
__device__ float g_aggS[NS*CC];
__device__ float g_aggG[NG*CC];
__device__ float g_aggW[NW*CC];
__device__ float g_aggT[NT*CC];
__device__ float g_degU[NU];
__device__ float g_degSu[NS];
__device__ float g_degSg[NS];
__device__ float g_degSw[NS];
__device__ float g_degSt[NS];
__device__ float g_degG[NG];
__device__ float g_degW[NW];
__device__ float g_degT[NT];
__device__ float g_WrS1[CC*CC];
__device__ float g_blS1[CC];
__device__ float g_WrS2[CC*CC];
__device__ float g_blS2[CC];

// ---------------- GEMM: C[m][n] (+)= scale(m) * sum_k A[m][k]*B[n][k] ------
// N fixed = 64. B is row-major [64][KT]. Optional bias[n], optional accumulate,
// optional per-row scale 1/max(deg[m],1) (fuses the mean division).
template<int KT, bool ACC, bool HAS_BIAS, bool HAS_SCALE>
__global__ void __launch_bounds__(256)
gemm_nt64(const float* __restrict__ A, const float* __restrict__ B,
          const float* __restrict__ bias, const float* __restrict__ deg,
          float* __restrict__ Cmat, int M)
{
    __shared__ float As[128][36];   // 128 x 32 K-tile, pad 36 (float4 aligned)
    __shared__ float Wt[32][65];    // transposed W tile, pad 65 (conflict-free)
    const int tid = threadIdx.x;
    const int m0 = blockIdx.x * 128;
    const int cg = tid & 7;         // cols cg*8 .. cg*8+7
    const int rg = tid >> 3;        // rows rg*4 .. rg*4+3

    float acc[4][8];
#pragma unroll
    for (int r = 0; r < 4; r++)
#pragma unroll
        for (int n = 0; n < 8; n++) acc[r][n] = 0.f;

    for (int k0 = 0; k0 < KT; k0 += 32) {
        // load A tile 128x32 (float4), apply row scale at load
#pragma unroll
        for (int it = 0; it < 4; it++) {
            int idx = it * 256 + tid;
            int row = idx >> 3;
            int c4  = (idx & 7) << 2;
            int m = m0 + row;
            float4 v = make_float4(0.f, 0.f, 0.f, 0.f);
            if (m < M) {
                v = *(const float4*)(A + (size_t)m * KT + k0 + c4);
                if (HAS_SCALE) {
                    float sc = 1.f / fmaxf(deg[m], 1.f);
                    v.x *= sc; v.y *= sc; v.z *= sc; v.w *= sc;
                }
            }
            *(float4*)&As[row][c4] = v;
        }
        // load + transpose B tile 64x32 -> Wt[kk][n]
#pragma unroll
        for (int it = 0; it < 2; it++) {
            int idx = it * 256 + tid;
            int row = idx >> 3;          // 0..63
            int c4  = (idx & 7) << 2;    // 0..28
            float4 v = *(const float4*)(B + (size_t)row * KT + k0 + c4);
            Wt[c4 + 0][row] = v.x;
            Wt[c4 + 1][row] = v.y;
            Wt[c4 + 2][row] = v.z;
            Wt[c4 + 3][row] = v.w;
        }
        __syncthreads();
#pragma unroll
        for (int kk = 0; kk < 32; kk++) {
            float a0 = As[rg * 4 + 0][kk];
            float a1 = As[rg * 4 + 1][kk];
            float a2 = As[rg * 4 + 2][kk];
            float a3 = As[rg * 4 + 3][kk];
#pragma unroll
            for (int n = 0; n < 8; n++) {
                float w = Wt[kk][cg * 8 + n];
                acc[0][n] += a0 * w;
                acc[1][n] += a1 * w;
                acc[2][n] += a2 * w;
                acc[3][n] += a3 * w;
            }
        }
        __syncthreads();
    }
#pragma unroll
    for (int r = 0; r < 4; r++) {
        int m = m0 + rg * 4 + r;
        if (m < M) {
            float* cp = Cmat + (size_t)m * CC + cg * 8;
#pragma unroll
            for (int h = 0; h < 2; h++) {
                float4 o = make_float4(acc[r][h*4+0], acc[r][h*4+1],
                                       acc[r][h*4+2], acc[r][h*4+3]);
                if (HAS_BIAS) {
                    o.x += bias[cg*8 + h*4 + 0];
                    o.y += bias[cg*8 + h*4 + 1];
                    o.z += bias[cg*8 + h*4 + 2];
                    o.w += bias[cg*8 + h*4 + 3];
                }
                if (ACC) {
                    float4 c0 = *(const float4*)(cp + h*4);
                    o.x += c0.x; o.y += c0.y; o.z += c0.z; o.w += c0.w;
                }
                *(float4*)(cp + h*4) = o;
            }
        }
    }
}

// ---------------- edge scatter: agg[dst] += x[src], float4 atomics ---------
__global__ void scatter_add(const float* __restrict__ x, const int* __restrict__ src,
                            const int* __restrict__ dst, int E, float* __restrict__ agg)
{
    int gid = blockIdx.x * blockDim.x + threadIdx.x;
    int e = gid >> 4;
    if (e >= E) return;
    int j = (gid & 15) << 2;
    int s = src[e];
    int d = dst[e];
    float4 v = *(const float4*)(x + (size_t)s * CC + j);
    atomicAdd((float4*)(agg + (size_t)d * CC + j), v);   // sm_90+ vector red
}

// ---------------- degree counting (both directions at once) ----------------
__global__ void deg_count(const int* __restrict__ a, const int* __restrict__ b, int E,
                          float* __restrict__ degA, float* __restrict__ degB)
{
    int e = blockIdx.x * blockDim.x + threadIdx.x;
    if (e < E) {
        atomicAdd(degA + a[e], 1.f);
        atomicAdd(degB + b[e], 1.f);
    }
}

// ---------------- summed Wr/bl for series dst (4 incoming edge types) ------
__global__ void weight_sums(const float* __restrict__ Wr1, const float* __restrict__ bl1,
                            const float* __restrict__ Wr2, const float* __restrict__ bl2)
{
    int i = blockIdx.x * blockDim.x + threadIdx.x;
    if (i < CC * CC) {
        g_WrS1[i] = Wr1[i] + Wr1[2*CC*CC + i] + Wr1[4*CC*CC + i] + Wr1[6*CC*CC + i];
        g_WrS2[i] = Wr2[i] + Wr2[2*CC*CC + i] + Wr2[4*CC*CC + i] + Wr2[6*CC*CC + i];
    }
    if (i < CC) {
        g_blS1[i] = bl1[i] + bl1[2*CC + i] + bl1[4*CC + i] + bl1[6*CC + i];
        g_blS2[i] = bl2[i] + bl2[2*CC + i] + bl2[4*CC + i] + bl2[6*CC + i];
    }
}

__global__ void relu_inplace(float* __restrict__ x, int n4)
{
    int i = blockIdx.x * blockDim.x + threadIdx.x;
    if (i < n4) {
        float4 v = ((float4*)x)[i];
        v.x = fmaxf(v.x, 0.f); v.y = fmaxf(v.y, 0.f);
        v.z = fmaxf(v.z, 0.f); v.w = fmaxf(v.w, 0.f);
        ((float4*)x)[i] = v;
    }
}

// ---------------- classifier: out[e] = dot64(xu[u[e]], xs[s[e]]) -----------
__global__ void dot_score(const float* __restrict__ xu, const float* __restrict__ xs,
                          const int* __restrict__ ui, const int* __restrict__ si,
                          float* __restrict__ out, int E)
{
    int gid = blockIdx.x * blockDim.x + threadIdx.x;
    int e = gid >> 4;
    int j = (gid & 15) << 2;
    int ec = (e < E) ? e : (E - 1);
    float4 a = *(const float4*)(xu + (size_t)ui[ec] * CC + j);
    float4 b = *(const float4*)(xs + (size_t)si[ec] * CC + j);
    float d = a.x*b.x + a.y*b.y + a.z*b.z + a.w*b.w;
    d += __shfl_xor_sync(0xffffffffu, d, 1);
    d += __shfl_xor_sync(0xffffffffu, d, 2);
    d += __shfl_xor_sync(0xffffffffu, d, 4);
    d += __shfl_xor_sync(0xffffffffu, d, 8);
    if ((gid & 15) == 0 && e < E) out[e] = d;
}

static inline int cdiv(int a, int b) { return (a + b - 1) / b; }

extern "C" void kernel_launch(void* const* d_in, const int* in_sizes, int n_in,
                              void* d_out, int out_size)
{
    const float* reviews  = (const float*)d_in[0];
    const float* overview = (const float*)d_in[1];
    const float* g_emb    = (const float*)d_in[2];
    const float* w_emb    = (const float*)d_in[3];
    const float* t_emb    = (const float*)d_in[4];
    const float* Wu  = (const float*)d_in[5];
    const float* bu  = (const float*)d_in[6];
    const float* Wsw = (const float*)d_in[7];
    const float* bs  = (const float*)d_in[8];
    const float* Wl1 = (const float*)d_in[9];
    const float* bl1 = (const float*)d_in[10];
    const float* Wr1 = (const float*)d_in[11];
    const float* Wl2 = (const float*)d_in[12];
    const float* bl2 = (const float*)d_in[13];
    const float* Wr2 = (const float*)d_in[14];
    const int* e_u2s = (const int*)d_in[15];
    const int* e_g2s = (const int*)d_in[16];
    const int* e_w2s = (const int*)d_in[17];
    const int* e_t2s = (const int*)d_in[18];
    const int* eli   = (const int*)d_in[19];
    float* out = (float*)d_out;

    float *xu,*xs,*yu,*ys,*xg,*xw,*xt;
    float *aggU,*aggS,*aggG,*aggW,*aggT;
    float *degU,*degSu,*degSg,*degSw,*degSt,*degG,*degW,*degT;
    float *WrS1,*blS1,*WrS2,*blS2;
    cudaGetSymbolAddress((void**)&xu,   g_xu);
    cudaGetSymbolAddress((void**)&xs,   g_xs);
    cudaGetSymbolAddress((void**)&yu,   g_yu);
    cudaGetSymbolAddress((void**)&ys,   g_ys);
    cudaGetSymbolAddress((void**)&xg,   g_xg);
    cudaGetSymbolAddress((void**)&xw,   g_xw);
    cudaGetSymbolAddress((void**)&xt,   g_xt);
    cudaGetSymbolAddress((void**)&aggU, g_aggU);
    cudaGetSymbolAddress((void**)&aggS, g_aggS);
    cudaGetSymbolAddress((void**)&aggG, g_aggG);
    cudaGetSymbolAddress((void**)&aggW, g_aggW);
    cudaGetSymbolAddress((void**)&aggT, g_aggT);
    cudaGetSymbolAddress((void**)&degU, g_degU);
    cudaGetSymbolAddress((void**)&degSu,g_degSu);
    cudaGetSymbolAddress((void**)&degSg,g_degSg);
    cudaGetSymbolAddress((void**)&degSw,g_degSw);
    cudaGetSymbolAddress((void**)&degSt,g_degSt);
    cudaGetSymbolAddress((void**)&degG, g_degG);
    cudaGetSymbolAddress((void**)&degW, g_degW);
    cudaGetSymbolAddress((void**)&degT, g_degT);
    cudaGetSymbolAddress((void**)&WrS1, g_WrS1);
    cudaGetSymbolAddress((void**)&blS1, g_blS1);
    cudaGetSymbolAddress((void**)&WrS2, g_WrS2);
    cudaGetSymbolAddress((void**)&blS2, g_blS2);

    const int gU = cdiv(NU, 128), gS = cdiv(NS, 128), gW = cdiv(NW, 128);

    // ---- phase 0: input feature transforms ----
    gemm_nt64<FF,false,true,false><<<gU,256>>>(reviews,  Wu,  bu, nullptr, xu, NU);
    gemm_nt64<FF,false,true,false><<<gS,256>>>(overview, Wsw, bs, nullptr, xs, NS);

    // ---- degrees + summed series weights ----
    cudaMemsetAsync(degU,  0, NU*sizeof(float));
    cudaMemsetAsync(degSu, 0, NS*sizeof(float));
    cudaMemsetAsync(degSg, 0, NS*sizeof(float));
    cudaMemsetAsync(degSw, 0, NS*sizeof(float));
    cudaMemsetAsync(degSt, 0, NS*sizeof(float));
    cudaMemsetAsync(degG,  0, NG*sizeof(float));
    cudaMemsetAsync(degW,  0, NW*sizeof(float));
    cudaMemsetAsync(degT,  0, NT*sizeof(float));
    deg_count<<<cdiv(E_US,256),256>>>(e_u2s, e_u2s+E_US, E_US, degU, degSu);
    deg_count<<<cdiv(E_GS,256),256>>>(e_g2s, e_g2s+E_GS, E_GS, degG, degSg);
    deg_count<<<cdiv(E_WS,256),256>>>(e_w2s, e_w2s+E_WS, E_WS, degW, degSw);
    deg_count<<<cdiv(E_TS,256),256>>>(e_t2s, e_t2s+E_TS, E_TS, degT, degSt);
    weight_sums<<<16,256>>>(Wr1, bl1, Wr2, bl2);

    const size_t SB = (size_t)NS*CC*sizeof(float);
    const size_t UB = (size_t)NU*CC*sizeof(float);

    // =================== layer 1 ===================
    // series -> ys
    gemm_nt64<CC,false,true,false><<<gS,256>>>(xs, WrS1, blS1, nullptr, ys, NS);
    cudaMemsetAsync(aggS, 0, SB);
    scatter_add<<<E_US*16/256,256>>>(xu, e_u2s, e_u2s+E_US, E_US, aggS);
    gemm_nt64<CC,true,false,true><<<gS,256>>>(aggS, Wl1+0*CC*CC, nullptr, degSu, ys, NS);
    cudaMemsetAsync(aggS, 0, SB);
    scatter_add<<<E_GS*16/256,256>>>(g_emb, e_g2s, e_g2s+E_GS, E_GS, aggS);
    gemm_nt64<CC,true,false,true><<<gS,256>>>(aggS, Wl1+2*CC*CC, nullptr, degSg, ys, NS);
    cudaMemsetAsync(aggS, 0, SB);
    scatter_add<<<E_WS*16/256,256>>>(w_emb, e_w2s, e_w2s+E_WS, E_WS, aggS);
    gemm_nt64<CC,true,false,true><<<gS,256>>>(aggS, Wl1+4*CC*CC, nullptr, degSw, ys, NS);
    cudaMemsetAsync(aggS, 0, SB);
    scatter_add<<<E_TS*16/256,256>>>(t_emb, e_t2s, e_t2s+E_TS, E_TS, aggS);
    gemm_nt64<CC,true,false,true><<<gS,256>>>(aggS, Wl1+6*CC*CC, nullptr, degSt, ys, NS);
    // users -> yu
    gemm_nt64<CC,false,true,false><<<gU,256>>>(xu, Wr1+1*CC*CC, bl1+1*CC, nullptr, yu, NU);
    cudaMemsetAsync(aggU, 0, UB);
    scatter_add<<<E_US*16/256,256>>>(xs, e_u2s+E_US, e_u2s, E_US, aggU);
    gemm_nt64<CC,true,false,true><<<gU,256>>>(aggU, Wl1+1*CC*CC, nullptr, degU, yu, NU);
    // genres -> xg
    gemm_nt64<CC,false,true,false><<<1,256>>>(g_emb, Wr1+3*CC*CC, bl1+3*CC, nullptr, xg, NG);
    cudaMemsetAsync(aggG, 0, (size_t)NG*CC*sizeof(float));
    scatter_add<<<E_GS*16/256,256>>>(xs, e_g2s+E_GS, e_g2s, E_GS, aggG);
    gemm_nt64<CC,true,false,true><<<1,256>>>(aggG, Wl1+3*CC*CC, nullptr, degG, xg, NG);
    // writer -> xw
    gemm_nt64<CC,false,true,false><<<gW,256>>>(w_emb, Wr1+5*CC*CC, bl1+5*CC, nullptr, xw, NW);
    cudaMemsetAsync(aggW, 0, (size_t)NW*CC*sizeof(float));
    scatter_add<<<E_WS*16/256,256>>>(xs, e_w2s+E_WS, e_w2s, E_WS, aggW);
    gemm_nt64<CC,true,false,true><<<gW,256>>>(aggW, Wl1+5*CC*CC, nullptr, degW, xw, NW);
    // type -> xt
    gemm_nt64<CC,false,true,false><<<1,256>>>(t_emb, Wr1+7*CC*CC, bl1+7*CC, nullptr, xt, NT);
    cudaMemsetAsync(aggT, 0, (size_t)NT*CC*sizeof(float));
    scatter_add<<<E_TS*16/256,256>>>(xs, e_t2s+E_TS, e_t2s, E_TS, aggT);
    gemm_nt64<CC,true,false,true><<<1,256>>>(aggT, Wl1+7*CC*CC, nullptr, degT, xt, NT);
    // relu all layer-1 outputs
    relu_inplace<<<cdiv(NS*CC/4,256),256>>>(ys, NS*CC/4);
    relu_inplace<<<cdiv(NU*CC/4,256),256>>>(yu, NU*CC/4);
    relu_inplace<<<cdiv(NG*CC/4,256),256>>>(xg, NG*CC/4);
    relu_inplace<<<cdiv(NW*CC/4,256),256>>>(xw, NW*CC/4);
    relu_inplace<<<cdiv(NT*CC/4,256),256>>>(xt, NT*CC/4);

    // =================== layer 2 (only users + series needed) ===================
    // series -> xs
    gemm_nt64<CC,false,true,false><<<gS,256>>>(ys, WrS2, blS2, nullptr, xs, NS);
    cudaMemsetAsync(aggS, 0, SB);
    scatter_add<<<E_US*16/256,256>>>(yu, e_u2s, e_u2s+E_US, E_US, aggS);
    gemm_nt64<CC,true,false,true><<<gS,256>>>(aggS, Wl2+0*CC*CC, nullptr, degSu, xs, NS);
    cudaMemsetAsync(aggS, 0, SB);
    scatter_add<<<E_GS*16/256,256>>>(xg, e_g2s, e_g2s+E_GS, E_GS, aggS);
    gemm_nt64<CC,true,false,true><<<gS,256>>>(aggS, Wl2+2*CC*CC, nullptr, degSg, xs, NS);
    cudaMemsetAsync(aggS, 0, SB);
    scatter_add<<<E_WS*16/256,256>>>(xw, e_w2s, e_w2s+E_WS, E_WS, aggS);
    gemm_nt64<CC,true,false,true><<<gS,256>>>(aggS, Wl2+4*CC*CC, nullptr, degSw, xs, NS);
    cudaMemsetAsync(aggS, 0, SB);
    scatter_add<<<E_TS*16/256,256>>>(xt, e_t2s, e_t2s+E_TS, E_TS, aggS);
    gemm_nt64<CC,true,false,true><<<gS,256>>>(aggS, Wl2+6*CC*CC, nullptr, degSt, xs, NS);
    // users -> xu
    gemm_nt64<CC,false,true,false><<<gU,256>>>(yu, Wr2+1*CC*CC, bl2+1*CC, nullptr, xu, NU);
    cudaMemsetAsync(aggU, 0, UB);
    scatter_add<<<E_US*16/256,256>>>(ys, e_u2s+E_US, e_u2s, E_US, aggU);
    gemm_nt64<CC,true,false,true><<<gU,256>>>(aggU, Wl2+1*CC*CC, nullptr, degU, xu, NU);

    // =================== classifier ===================
    dot_score<<<E_LI*16/256,256>>>(xu, xs, eli, eli+E_LI, out, E_LI);
}

// round 2
// speedup vs baseline: 1.5584x; 1.5584x over previous
#include <cuda_runtime.h>
#include <cstdint>

#define NU 100000
#define NS 50000
#define NG 50
#define NW 20000
#define NT 10
#define CC 64
#define FF 384
#define E_US 1000000
#define E_GS 150000
#define E_WS 50000
#define E_TS 50000
#define E_LI 200000

// ---- concatenated degree buffer layout ----
#define DEG_U   0
#define DEG_SU  (NU)
#define DEG_SG  (NU+NS)
#define DEG_SW  (NU+2*NS)
#define DEG_ST  (NU+3*NS)
#define DEG_G   (NU+4*NS)
#define DEG_W   (NU+4*NS+NG)
#define DEG_T   (NU+4*NS+NG+NW)
#define DEG_TOT (NU+4*NS+NG+NW+NT)

// ---- concatenated aggregation buffer layout ----
#define AGG_U 0
#define AGG_S ((size_t)NU*CC)
#define AGG_G ((size_t)(NU+NS)*CC)
#define AGG_W ((size_t)(NU+NS+NG)*CC)
#define AGG_T ((size_t)(NU+NS+NG+NW)*CC)
#define AGG_TOT ((size_t)(NU+NS+NG+NW+NT)*CC)

// ---------------- scratch (device globals; allocation-free) ----------------
__device__ float g_deg[DEG_TOT];
__device__ float g_agg[AGG_TOT];
__device__ float g_xu[NU*CC], g_xs[NS*CC];          // phase0 outputs
__device__ float g_yu[NU*CC], g_ys[NS*CC];          // layer1 outputs (relu'd)
__device__ float g_xg[NG*CC], g_xw[NW*CC], g_xt[NT*CC];
__device__ float g_xu2[NU*CC], g_xs2[NS*CC];        // layer2 outputs
__device__ float g_tS[NS*CC], g_tW[NW*CC], g_tG[NG*CC], g_tT[NT*CC];     // L1 pre-transforms
__device__ float g_tS2[NS*CC], g_tW2[NW*CC], g_tG2[NG*CC], g_tT2[NT*CC]; // L2 pre-transforms
__device__ float g_WrS1[CC*CC], g_blS1[CC], g_WrS2[CC*CC], g_blS2[CC];

// ---------------- tf32 helpers ----------------
__device__ __forceinline__ uint32_t f2tf(float x) {
    uint32_t r; asm("cvt.rna.tf32.f32 %0, %1;" : "=r"(r) : "f"(x)); return r;
}
__device__ __forceinline__ void mma8(float* d, const uint32_t* a, uint32_t b0, uint32_t b1) {
    asm("mma.sync.aligned.m16n8k8.row.col.f32.tf32.tf32.f32 "
        "{%0,%1,%2,%3}, {%4,%5,%6,%7}, {%8,%9}, {%0,%1,%2,%3};"
        : "+f"(d[0]), "+f"(d[1]), "+f"(d[2]), "+f"(d[3])
        : "r"(a[0]), "r"(a[1]), "r"(a[2]), "r"(a[3]), "r"(b0), "r"(b1));
}

// ---------------- batched GEMM: out[m][n] = f( scale(m)*(A@W^T) + bias + accin ) ----
// A: [M][KT] row-major, W: [64][KT] row-major. 3xTF32 split for fp32-class accuracy.
struct GemmJob {
    const float* A; const float* W; const float* bias; const float* accin;
    const float* deg; float* out; int M; int relu;
};
struct GemmJobs { GemmJob j[8]; };

template<int KT>
__global__ void __launch_bounds__(256) gemm_mma(const GemmJobs jobs)
{
    const GemmJob jb = jobs.j[blockIdx.y];
    const int m0 = blockIdx.x * 128;
    if (m0 >= jb.M) return;

    __shared__ float2 Wp[64][68];   // (hi,lo) tf32 pair; pitch 68 -> conflict-free frag loads

    const int tid = threadIdx.x, wid = tid >> 5, lane = tid & 31;
    const int g = lane >> 2, tg = lane & 3;

    float acc[8][4];
#pragma unroll
    for (int j = 0; j < 8; j++) { acc[j][0]=acc[j][1]=acc[j][2]=acc[j][3]=0.f; }

    const int mtop = jb.M - 1;
    const int mr0 = m0 + wid * 16 + g;          // rows mr0 and mr0+8
    const float* A0 = jb.A + (size_t)min(mr0,     mtop) * KT;
    const float* A1 = jb.A + (size_t)min(mr0 + 8, mtop) * KT;

    for (int k0 = 0; k0 < KT; k0 += 64) {
        __syncthreads();
        // stage W k-tile as (hi,lo) tf32 pairs
#pragma unroll
        for (int i = tid; i < 64 * 64; i += 256) {
            int n = i >> 6, k = i & 63;
            float w = jb.W[(size_t)n * KT + k0 + k];
            uint32_t hi = f2tf(w);
            float lo = w - __uint_as_float(hi);
            Wp[n][k] = make_float2(__uint_as_float(hi), __uint_as_float(f2tf(lo)));
        }
        __syncthreads();
#pragma unroll
        for (int ks = 0; ks < 8; ks++) {
            const int kk = k0 + ks * 8;
            float af[4] = { A0[kk+tg], A1[kk+tg], A0[kk+tg+4], A1[kk+tg+4] };
            uint32_t ah[4], al[4];
#pragma unroll
            for (int q = 0; q < 4; q++) {
                ah[q] = f2tf(af[q]);
                al[q] = f2tf(af[q] - __uint_as_float(ah[q]));
            }
#pragma unroll
            for (int j = 0; j < 8; j++) {
                float2 b0 = Wp[j*8 + g][ks*8 + tg];
                float2 b1 = Wp[j*8 + g][ks*8 + tg + 4];
                uint32_t bh0 = __float_as_uint(b0.x), bl0 = __float_as_uint(b0.y);
                uint32_t bh1 = __float_as_uint(b1.x), bl1 = __float_as_uint(b1.y);
                mma8(acc[j], ah, bh0, bh1);   // hi*hi
                mma8(acc[j], al, bh0, bh1);   // lo*hi
                mma8(acc[j], ah, bl0, bl1);   // hi*lo
            }
        }
    }

    // epilogue
    const float s0 = jb.deg ? 1.f / fmaxf(jb.deg[min(mr0,     mtop)], 1.f) : 1.f;
    const float s1 = jb.deg ? 1.f / fmaxf(jb.deg[min(mr0 + 8, mtop)], 1.f) : 1.f;
#pragma unroll
    for (int j = 0; j < 8; j++) {
        const int n = j * 8 + 2 * tg;
        float bv0 = 0.f, bv1 = 0.f;
        if (jb.bias) { bv0 = jb.bias[n]; bv1 = jb.bias[n + 1]; }
        if (mr0 < jb.M) {
            float v0 = acc[j][0] * s0 + bv0;
            float v1 = acc[j][1] * s0 + bv1;
            if (jb.accin) {
                v0 += jb.accin[(size_t)mr0 * CC + n];
                v1 += jb.accin[(size_t)mr0 * CC + n + 1];
            }
            if (jb.relu) { v0 = fmaxf(v0, 0.f); v1 = fmaxf(v1, 0.f); }
            *(float2*)(jb.out + (size_t)mr0 * CC + n) = make_float2(v0, v1);
        }
        if (mr0 + 8 < jb.M) {
            float v0 = acc[j][2] * s1 + bv0;
            float v1 = acc[j][3] * s1 + bv1;
            if (jb.accin) {
                v0 += jb.accin[(size_t)(mr0 + 8) * CC + n];
                v1 += jb.accin[(size_t)(mr0 + 8) * CC + n + 1];
            }
            if (jb.relu) { v0 = fmaxf(v0, 0.f); v1 = fmaxf(v1, 0.f); }
            *(float2*)(jb.out + (size_t)(mr0 + 8) * CC + n) = make_float2(v0, v1);
        }
    }
}

// ---------------- batched scatter: out[dst] += (x[src]) * (scale? 1/max(deg[dst],1):1) ----
struct ScatJob { const float* x; const int* src; const int* dst; const float* scale; float* out; };
struct ScatJobs { ScatJob j[8]; int off[9]; int n; };

__global__ void __launch_bounds__(256) scatter_multi(const ScatJobs js)
{
    int gid = blockIdx.x * 256 + threadIdx.x;
    int ge = gid >> 2;                 // 4 threads per edge, 16 floats each
    if (ge >= js.off[js.n]) return;
    int part = gid & 3;
    int jj = 0;
    while (ge >= js.off[jj + 1]) jj++;
    const ScatJob jb = js.j[jj];
    int e = ge - js.off[jj];
    int s = jb.src[e], d = jb.dst[e];
    const float4* xp = (const float4*)(jb.x + (size_t)s * CC) + part * 4;
    float4*       op = (float4*)(jb.out + (size_t)d * CC) + part * 4;
    if (jb.scale) {
        float sc = 1.f / fmaxf(jb.scale[d], 1.f);
#pragma unroll
        for (int q = 0; q < 4; q++) {
            float4 v = xp[q];
            v.x *= sc; v.y *= sc; v.z *= sc; v.w *= sc;
            atomicAdd(op + q, v);
        }
    } else {
#pragma unroll
        for (int q = 0; q < 4; q++) atomicAdd(op + q, xp[q]);
    }
}

// ---------------- fused degree counting over all 4 edge lists ----------------
__global__ void deg_all(const int* u2s, const int* g2s, const int* w2s, const int* t2s,
                        float* __restrict__ deg)
{
    int i = blockIdx.x * blockDim.x + threadIdx.x;
    if (i < E_US) { atomicAdd(deg + DEG_U  + u2s[i], 1.f); atomicAdd(deg + DEG_SU + u2s[E_US + i], 1.f); }
    if (i < E_GS) { atomicAdd(deg + DEG_G  + g2s[i], 1.f); atomicAdd(deg + DEG_SG + g2s[E_GS + i], 1.f); }
    if (i < E_WS) { atomicAdd(deg + DEG_W  + w2s[i], 1.f); atomicAdd(deg + DEG_SW + w2s[E_WS + i], 1.f); }
    if (i < E_TS) { atomicAdd(deg + DEG_T  + t2s[i], 1.f); atomicAdd(deg + DEG_ST + t2s[E_TS + i], 1.f); }
}

// ---------------- summed Wr/bl for series dst (4 incoming edge types) ------
__global__ void weight_sums(const float* __restrict__ Wr1, const float* __restrict__ bl1,
                            const float* __restrict__ Wr2, const float* __restrict__ bl2)
{
    int i = blockIdx.x * blockDim.x + threadIdx.x;
    if (i < CC * CC) {
        g_WrS1[i] = Wr1[i] + Wr1[2*CC*CC + i] + Wr1[4*CC*CC + i] + Wr1[6*CC*CC + i];
        g_WrS2[i] = Wr2[i] + Wr2[2*CC*CC + i] + Wr2[4*CC*CC + i] + Wr2[6*CC*CC + i];
    }
    if (i < CC) {
        g_blS1[i] = bl1[i] + bl1[2*CC + i] + bl1[4*CC + i] + bl1[6*CC + i];
        g_blS2[i] = bl2[i] + bl2[2*CC + i] + bl2[4*CC + i] + bl2[6*CC + i];
    }
}

// ---------------- classifier: out[e] = dot64(xu[u[e]], xs[s[e]]) -----------
__global__ void dot_score(const float* __restrict__ xu, const float* __restrict__ xs,
                          const int* __restrict__ ui, const int* __restrict__ si,
                          float* __restrict__ out, int E)
{
    int gid = blockIdx.x * blockDim.x + threadIdx.x;
    int e = gid >> 4;
    int j = (gid & 15) << 2;
    int ec = (e < E) ? e : (E - 1);
    float4 a = *(const float4*)(xu + (size_t)ui[ec] * CC + j);
    float4 b = *(const float4*)(xs + (size_t)si[ec] * CC + j);
    float d = a.x*b.x + a.y*b.y + a.z*b.z + a.w*b.w;
    d += __shfl_xor_sync(0xffffffffu, d, 1);
    d += __shfl_xor_sync(0xffffffffu, d, 2);
    d += __shfl_xor_sync(0xffffffffu, d, 4);
    d += __shfl_xor_sync(0xffffffffu, d, 8);
    if ((gid & 15) == 0 && e < E) out[e] = d;
}

static inline int cdiv(int a, int b) { return (a + b - 1) / b; }

extern "C" void kernel_launch(void* const* d_in, const int* in_sizes, int n_in,
                              void* d_out, int out_size)
{
    const float* reviews  = (const float*)d_in[0];
    const float* overview = (const float*)d_in[1];
    const float* g_emb    = (const float*)d_in[2];
    const float* w_emb    = (const float*)d_in[3];
    const float* t_emb    = (const float*)d_in[4];
    const float* Wu  = (const float*)d_in[5];
    const float* bu  = (const float*)d_in[6];
    const float* Wsw = (const float*)d_in[7];
    const float* bs  = (const float*)d_in[8];
    const float* Wl1 = (const float*)d_in[9];
    const float* bl1 = (const float*)d_in[10];
    const float* Wr1 = (const float*)d_in[11];
    const float* Wl2 = (const float*)d_in[12];
    const float* bl2 = (const float*)d_in[13];
    const float* Wr2 = (const float*)d_in[14];
    const int* e_u2s = (const int*)d_in[15];
    const int* e_g2s = (const int*)d_in[16];
    const int* e_w2s = (const int*)d_in[17];
    const int* e_t2s = (const int*)d_in[18];
    const int* eli   = (const int*)d_in[19];
    float* out = (float*)d_out;

    float *deg,*agg,*xu,*xs,*yu,*ys,*xg,*xw,*xt,*xu2,*xs2;
    float *tS,*tW,*tG,*tT,*tS2,*tW2,*tG2,*tT2,*WrS1,*blS1,*WrS2,*blS2;
    cudaGetSymbolAddress((void**)&deg,  g_deg);
    cudaGetSymbolAddress((void**)&agg,  g_agg);
    cudaGetSymbolAddress((void**)&xu,   g_xu);
    cudaGetSymbolAddress((void**)&xs,   g_xs);
    cudaGetSymbolAddress((void**)&yu,   g_yu);
    cudaGetSymbolAddress((void**)&ys,   g_ys);
    cudaGetSymbolAddress((void**)&xg,   g_xg);
    cudaGetSymbolAddress((void**)&xw,   g_xw);
    cudaGetSymbolAddress((void**)&xt,   g_xt);
    cudaGetSymbolAddress((void**)&xu2,  g_xu2);
    cudaGetSymbolAddress((void**)&xs2,  g_xs2);
    cudaGetSymbolAddress((void**)&tS,   g_tS);
    cudaGetSymbolAddress((void**)&tW,   g_tW);
    cudaGetSymbolAddress((void**)&tG,   g_tG);
    cudaGetSymbolAddress((void**)&tT,   g_tT);
    cudaGetSymbolAddress((void**)&tS2,  g_tS2);
    cudaGetSymbolAddress((void**)&tW2,  g_tW2);
    cudaGetSymbolAddress((void**)&tG2,  g_tG2);
    cudaGetSymbolAddress((void**)&tT2,  g_tT2);
    cudaGetSymbolAddress((void**)&WrS1, g_WrS1);
    cudaGetSymbolAddress((void**)&blS1, g_blS1);
    cudaGetSymbolAddress((void**)&WrS2, g_WrS2);
    cudaGetSymbolAddress((void**)&blS2, g_blS2);

    const int W44 = CC*CC;  // 4096 floats per weight matrix

    // ---- init: zero deg + agg, count degrees, sum series weights ----
    cudaMemsetAsync(deg, 0, DEG_TOT * sizeof(float));
    cudaMemsetAsync(agg, 0, AGG_TOT * sizeof(float));
    deg_all<<<cdiv(E_US,256),256>>>(e_u2s, e_g2s, e_w2s, e_t2s, deg);
    weight_sums<<<16,256>>>(Wr1, bl1, Wr2, bl2);

    // ---- phase 0: input transforms (batched, K=384) ----
    {
        GemmJobs P{};
        P.j[0] = { reviews,  Wu,  bu, nullptr, nullptr, xu, NU, 0 };
        P.j[1] = { overview, Wsw, bs, nullptr, nullptr, xs, NS, 0 };
        gemm_mma<FF><<<dim3(cdiv(NU,128), 2), 256>>>(P);
    }

    // ---- wave A: all independent K=64 GEMMs for layer 1 ----
    {
        GemmJobs A{};
        A.j[0] = { xs,    WrS1,        blS1,       nullptr, nullptr, ys, NS, 0 }; // series self
        A.j[1] = { xs,    Wl1 + 1*W44, nullptr,    nullptr, nullptr, tS, NS, 0 }; // s->u pre
        A.j[2] = { w_emb, Wl1 + 4*W44, nullptr,    nullptr, nullptr, tW, NW, 0 }; // w->s pre
        A.j[3] = { w_emb, Wr1 + 5*W44, bl1 + 5*CC, nullptr, nullptr, xw, NW, 0 }; // writer self
        A.j[4] = { g_emb, Wl1 + 2*W44, nullptr,    nullptr, nullptr, tG, NG, 0 }; // g->s pre
        A.j[5] = { g_emb, Wr1 + 3*W44, bl1 + 3*CC, nullptr, nullptr, xg, NG, 0 }; // genres self
        A.j[6] = { t_emb, Wl1 + 6*W44, nullptr,    nullptr, nullptr, tT, NT, 0 }; // t->s pre
        A.j[7] = { t_emb, Wr1 + 7*W44, bl1 + 7*CC, nullptr, nullptr, xt, NT, 0 }; // type self
        gemm_mma<CC><<<dim3(cdiv(NS,128), 8), 256>>>(A);
    }

    // ---- scatter wave A (all 8 edge flows of layer 1) ----
    {
        ScatJobs S{};
        S.j[0] = { xu, e_u2s,        e_u2s + E_US, nullptr,      agg + AGG_S }; // u->s post
        S.j[1] = { tS, e_u2s + E_US, e_u2s,        deg + DEG_U,  agg + AGG_U }; // s->u pre (scaled)
        S.j[2] = { tG, e_g2s,        e_g2s + E_GS, deg + DEG_SG, ys };          // g->s pre into ys
        S.j[3] = { xs, e_g2s + E_GS, e_g2s,        nullptr,      agg + AGG_G }; // s->g post
        S.j[4] = { tW, e_w2s,        e_w2s + E_WS, deg + DEG_SW, ys };          // w->s pre into ys
        S.j[5] = { xs, e_w2s + E_WS, e_w2s,        nullptr,      agg + AGG_W }; // s->w post
        S.j[6] = { tT, e_t2s,        e_t2s + E_TS, deg + DEG_ST, ys };          // t->s pre into ys
        S.j[7] = { xs, e_t2s + E_TS, e_t2s,        nullptr,      agg + AGG_T }; // s->t post
        int o = 0;
        S.off[0]=o; o+=E_US; S.off[1]=o; o+=E_US; S.off[2]=o; o+=E_GS; S.off[3]=o; o+=E_GS;
        S.off[4]=o; o+=E_WS; S.off[5]=o; o+=E_WS; S.off[6]=o; o+=E_TS; S.off[7]=o; o+=E_TS;
        S.off[8]=o; S.n = 8;
        scatter_multi<<<cdiv(o*4,256),256>>>(S);
    }

    // ---- wave B: finalize layer 1 (post GEMMs with accumulate + relu) ----
    {
        GemmJobs B{};
        B.j[0] = { agg + AGG_S, Wl1 + 0*W44, nullptr,    ys,          deg + DEG_SU, ys, NS, 1 };
        B.j[1] = { xu,          Wr1 + 1*W44, bl1 + 1*CC, agg + AGG_U, nullptr,      yu, NU, 1 };
        B.j[2] = { agg + AGG_G, Wl1 + 3*W44, nullptr,    xg,          deg + DEG_G,  xg, NG, 1 };
        B.j[3] = { agg + AGG_W, Wl1 + 5*W44, nullptr,    xw,          deg + DEG_W,  xw, NW, 1 };
        B.j[4] = { agg + AGG_T, Wl1 + 7*W44, nullptr,    xt,          deg + DEG_T,  xt, NT, 1 };
        gemm_mma<CC><<<dim3(cdiv(NU,128), 5), 256>>>(B);
    }

    // ---- wave C: layer 2 independent GEMMs (only users+series outputs needed) ----
    {
        GemmJobs Cj{};
        Cj.j[0] = { ys, WrS2,        blS2,       nullptr, nullptr, xs2, NS, 0 };
        Cj.j[1] = { ys, Wl2 + 1*W44, nullptr,    nullptr, nullptr, tS2, NS, 0 };
        Cj.j[2] = { xw, Wl2 + 4*W44, nullptr,    nullptr, nullptr, tW2, NW, 0 };
        Cj.j[3] = { xg, Wl2 + 2*W44, nullptr,    nullptr, nullptr, tG2, NG, 0 };
        Cj.j[4] = { xt, Wl2 + 6*W44, nullptr,    nullptr, nullptr, tT2, NT, 0 };
        Cj.j[5] = { yu, Wr2 + 1*W44, bl2 + 1*CC, nullptr, nullptr, xu2, NU, 0 };
        gemm_mma<CC><<<dim3(cdiv(NU,128), 6), 256>>>(Cj);
    }

    // ---- re-zero series agg, scatter wave C ----
    cudaMemsetAsync(agg + AGG_S, 0, (size_t)NS * CC * sizeof(float));
    {
        ScatJobs S{};
        S.j[0] = { yu,  e_u2s,        e_u2s + E_US, nullptr,      agg + AGG_S }; // u->s post
        S.j[1] = { tS2, e_u2s + E_US, e_u2s,        deg + DEG_U,  xu2 };         // s->u pre into xu2
        S.j[2] = { tG2, e_g2s,        e_g2s + E_GS, deg + DEG_SG, xs2 };
        S.j[3] = { tW2, e_w2s,        e_w2s + E_WS, deg + DEG_SW, xs2 };
        S.j[4] = { tT2, e_t2s,        e_t2s + E_TS, deg + DEG_ST, xs2 };
        int o = 0;
        S.off[0]=o; o+=E_US; S.off[1]=o; o+=E_US; S.off[2]=o; o+=E_GS;
        S.off[3]=o; o+=E_WS; S.off[4]=o; o+=E_TS; S.off[5]=o;
        S.n = 5;
        scatter_multi<<<cdiv(o*4,256),256>>>(S);
    }

    // ---- wave D: final series accumulate ----
    {
        GemmJobs D{};
        D.j[0] = { agg + AGG_S, Wl2 + 0*W44, nullptr, xs2, deg + DEG_SU, xs2, NS, 0 };
        gemm_mma<CC><<<dim3(cdiv(NS,128), 1), 256>>>(D);
    }

    // ---- classifier ----
    dot_score<<<E_LI*16/256,256>>>(xu2, xs2, eli, eli + E_LI, out, E_LI);
}

// round 3
// speedup vs baseline: 1.7322x; 1.1115x over previous
#include <cuda_runtime.h>
#include <cuda_bf16.h>
#include <cstdint>

#define NU 100000
#define NS 50000
#define NG 50
#define NW 20000
#define NT 10
#define CC 64
#define FF 384
#define E_US 1000000
#define E_GS 150000
#define E_WS 50000
#define E_TS 50000
#define E_LI 200000

// ---- concatenated degree buffer layout ----
#define DEG_U   0
#define DEG_SU  (NU)
#define DEG_SG  (NU+NS)
#define DEG_SW  (NU+2*NS)
#define DEG_ST  (NU+3*NS)
#define DEG_G   (NU+4*NS)
#define DEG_W   (NU+4*NS+NG)
#define DEG_T   (NU+4*NS+NG+NW)
#define DEG_TOT (NU+4*NS+NG+NW+NT)

// ---- concatenated aggregation buffer layout ----
#define AGG_U 0
#define AGG_S ((size_t)NU*CC)
#define AGG_G ((size_t)(NU+NS)*CC)
#define AGG_W ((size_t)(NU+NS+NG)*CC)
#define AGG_T ((size_t)(NU+NS+NG+NW)*CC)
#define AGG_TOT ((size_t)(NU+NS+NG+NW+NT)*CC)

// ---------------- scratch (device globals; allocation-free) ----------------
__device__ float g_deg[DEG_TOT];
__device__ float g_agg[AGG_TOT];
__device__ float g_xu[NU*CC], g_xs[NS*CC];
__device__ float g_yu[NU*CC], g_ys[NS*CC];
__device__ float g_xg[NG*CC], g_xw[NW*CC], g_xt[NT*CC];
__device__ float g_xu2[NU*CC], g_xs2[NS*CC];
__device__ float g_tS[NS*CC], g_tW[NW*CC], g_tG[NG*CC], g_tT[NT*CC];
__device__ float g_tS2[NS*CC], g_tW2[NW*CC], g_tG2[NG*CC], g_tT2[NT*CC];
__device__ float g_WrS1[CC*CC], g_blS1[CC], g_WrS2[CC*CC], g_blS2[CC];

// ---------------- bf16 split helpers ----------------
__device__ __forceinline__ uint32_t packbf(float x, float y) {
    __nv_bfloat162 h = __floats2bfloat162_rn(x, y);
    return *(uint32_t*)&h;
}
__device__ __forceinline__ void split2(float x, float y, uint32_t& hi, uint32_t& lo) {
    __nv_bfloat162 h = __floats2bfloat162_rn(x, y);
    float2 hf = __bfloat1622float2(h);
    __nv_bfloat162 l = __floats2bfloat162_rn(x - hf.x, y - hf.y);
    hi = *(uint32_t*)&h;
    lo = *(uint32_t*)&l;
}
__device__ __forceinline__ void mma16(float* d, const uint32_t* a, uint32_t b0, uint32_t b1) {
    asm("mma.sync.aligned.m16n8k16.row.col.f32.bf16.bf16.f32 "
        "{%0,%1,%2,%3}, {%4,%5,%6,%7}, {%8,%9}, {%0,%1,%2,%3};"
        : "+f"(d[0]), "+f"(d[1]), "+f"(d[2]), "+f"(d[3])
        : "r"(a[0]), "r"(a[1]), "r"(a[2]), "r"(a[3]), "r"(b0), "r"(b1));
}

// ---------------- batched GEMM: out[m][n] = f( scale(m)*(A@W^T) + bias + accin ) ----
struct GemmJob {
    const float* A; const float* W; const float* bias; const float* accin;
    const float* deg; float* out; int M; int relu;
};
struct GemmJobs { GemmJob j[8]; };

template<int KT>
__device__ __forceinline__ void gemm_body(const GemmJob& jb)
{
    const int m0 = blockIdx.x * 128;
    if (m0 >= jb.M) return;

    __shared__ uint32_t Whi[64][36];   // bf16x2 pairs, pitch 36 -> conflict-free
    __shared__ uint32_t Wlo[64][36];

    const int tid = threadIdx.x, wid = tid >> 5, lane = tid & 31;
    const int g = lane >> 2, tg = lane & 3;

    float acc[8][4];
#pragma unroll
    for (int j = 0; j < 8; j++) { acc[j][0]=acc[j][1]=acc[j][2]=acc[j][3]=0.f; }

    const int mtop = jb.M - 1;
    const int mr0 = m0 + wid * 16 + g;          // rows mr0 and mr0+8
    const float* A0 = jb.A + (size_t)min(mr0,     mtop) * KT;
    const float* A1 = jb.A + (size_t)min(mr0 + 8, mtop) * KT;

    for (int k0 = 0; k0 < KT; k0 += 64) {
        if (k0) __syncthreads();
        // stage W k-tile as bf16 (hi,lo) pairs
#pragma unroll
        for (int i = tid; i < 64 * 32; i += 256) {
            int n = i >> 5, kp = i & 31;
            float2 w = *(const float2*)(jb.W + (size_t)n * KT + k0 + 2 * kp);
            split2(w.x, w.y, Whi[n][kp], Wlo[n][kp]);
        }
        __syncthreads();
#pragma unroll
        for (int ks = 0; ks < 4; ks++) {
            const int kk = k0 + ks * 16 + 2 * tg;
            float2 a00 = *(const float2*)(A0 + kk);
            float2 a10 = *(const float2*)(A1 + kk);
            float2 a01 = *(const float2*)(A0 + kk + 8);
            float2 a11 = *(const float2*)(A1 + kk + 8);
            uint32_t ah[4], al[4];
            split2(a00.x, a00.y, ah[0], al[0]);
            split2(a10.x, a10.y, ah[1], al[1]);
            split2(a01.x, a01.y, ah[2], al[2]);
            split2(a11.x, a11.y, ah[3], al[3]);
#pragma unroll
            for (int j = 0; j < 8; j++) {
                uint32_t bh0 = Whi[j*8 + g][ks*8 + tg];
                uint32_t bh1 = Whi[j*8 + g][ks*8 + tg + 4];
                uint32_t bl0 = Wlo[j*8 + g][ks*8 + tg];
                uint32_t bl1 = Wlo[j*8 + g][ks*8 + tg + 4];
                mma16(acc[j], ah, bh0, bh1);   // hi*hi
                mma16(acc[j], al, bh0, bh1);   // lo*hi
                mma16(acc[j], ah, bl0, bl1);   // hi*lo
            }
        }
    }

    // epilogue
    const float s0 = jb.deg ? 1.f / fmaxf(jb.deg[min(mr0,     mtop)], 1.f) : 1.f;
    const float s1 = jb.deg ? 1.f / fmaxf(jb.deg[min(mr0 + 8, mtop)], 1.f) : 1.f;
#pragma unroll
    for (int j = 0; j < 8; j++) {
        const int n = j * 8 + 2 * tg;
        float bv0 = 0.f, bv1 = 0.f;
        if (jb.bias) { bv0 = jb.bias[n]; bv1 = jb.bias[n + 1]; }
        if (mr0 < jb.M) {
            float v0 = acc[j][0] * s0 + bv0;
            float v1 = acc[j][1] * s0 + bv1;
            if (jb.accin) {
                float2 c = *(const float2*)(jb.accin + (size_t)mr0 * CC + n);
                v0 += c.x; v1 += c.y;
            }
            if (jb.relu) { v0 = fmaxf(v0, 0.f); v1 = fmaxf(v1, 0.f); }
            *(float2*)(jb.out + (size_t)mr0 * CC + n) = make_float2(v0, v1);
        }
        if (mr0 + 8 < jb.M) {
            float v0 = acc[j][2] * s1 + bv0;
            float v1 = acc[j][3] * s1 + bv1;
            if (jb.accin) {
                float2 c = *(const float2*)(jb.accin + (size_t)(mr0 + 8) * CC + n);
                v0 += c.x; v1 += c.y;
            }
            if (jb.relu) { v0 = fmaxf(v0, 0.f); v1 = fmaxf(v1, 0.f); }
            *(float2*)(jb.out + (size_t)(mr0 + 8) * CC + n) = make_float2(v0, v1);
        }
    }
}

template<int KT>
__global__ void __launch_bounds__(256) gemm_mma(const GemmJobs jobs)
{
    gemm_body<KT>(jobs.j[blockIdx.y]);
}

// phase0 + degree counting + weight sums fused (deg work hides under the GEMM)
__global__ void __launch_bounds__(256) phase0_fused(
    const GemmJobs jobs,
    const int* __restrict__ u2s, const int* __restrict__ g2s,
    const int* __restrict__ w2s, const int* __restrict__ t2s,
    float* __restrict__ deg,
    const float* __restrict__ Wr1, const float* __restrict__ bl1,
    const float* __restrict__ Wr2, const float* __restrict__ bl2)
{
    if (blockIdx.y == 2) {
        const int stride = gridDim.x * 256;
        int base = blockIdx.x * 256 + threadIdx.x;
        for (int i = base; i < E_US; i += stride) {
            atomicAdd(deg + DEG_U  + u2s[i], 1.f);
            atomicAdd(deg + DEG_SU + u2s[E_US + i], 1.f);
        }
        for (int i = base; i < E_GS; i += stride) {
            atomicAdd(deg + DEG_G  + g2s[i], 1.f);
            atomicAdd(deg + DEG_SG + g2s[E_GS + i], 1.f);
        }
        for (int i = base; i < E_WS; i += stride) {
            atomicAdd(deg + DEG_W  + w2s[i], 1.f);
            atomicAdd(deg + DEG_SW + w2s[E_WS + i], 1.f);
        }
        for (int i = base; i < E_TS; i += stride) {
            atomicAdd(deg + DEG_T  + t2s[i], 1.f);
            atomicAdd(deg + DEG_ST + t2s[E_TS + i], 1.f);
        }
        if (blockIdx.x == 0) {
            for (int i = threadIdx.x; i < CC * CC; i += 256) {
                g_WrS1[i] = Wr1[i] + Wr1[2*CC*CC + i] + Wr1[4*CC*CC + i] + Wr1[6*CC*CC + i];
                g_WrS2[i] = Wr2[i] + Wr2[2*CC*CC + i] + Wr2[4*CC*CC + i] + Wr2[6*CC*CC + i];
            }
            if (threadIdx.x < CC) {
                int i = threadIdx.x;
                g_blS1[i] = bl1[i] + bl1[2*CC + i] + bl1[4*CC + i] + bl1[6*CC + i];
                g_blS2[i] = bl2[i] + bl2[2*CC + i] + bl2[4*CC + i] + bl2[6*CC + i];
            }
        }
        return;
    }
    gemm_body<FF>(jobs.j[blockIdx.y]);
}

// ---------------- batched scatter: out[dst] += x[src] * (scale? 1/max(deg[dst],1):1) ----
struct ScatJob { const float* x; const int* src; const int* dst; const float* scale; float* out; };
struct ScatJobs { ScatJob j[8]; int off[9]; int n; };

__global__ void __launch_bounds__(256) scatter_multi(const ScatJobs js)
{
    int gid = blockIdx.x * 256 + threadIdx.x;
    int ge = gid >> 2;                 // 4 threads per edge, 16 floats each
    if (ge >= js.off[js.n]) return;
    int part = gid & 3;
    int jj = 0;
    while (ge >= js.off[jj + 1]) jj++;
    const ScatJob jb = js.j[jj];
    int e = ge - js.off[jj];
    int s = jb.src[e], d = jb.dst[e];
    const float4* xp = (const float4*)(jb.x + (size_t)s * CC) + part * 4;
    float4*       op = (float4*)(jb.out + (size_t)d * CC) + part * 4;
    if (jb.scale) {
        float sc = 1.f / fmaxf(jb.scale[d], 1.f);
#pragma unroll
        for (int q = 0; q < 4; q++) {
            float4 v = xp[q];
            v.x *= sc; v.y *= sc; v.z *= sc; v.w *= sc;
            atomicAdd(op + q, v);
        }
    } else {
#pragma unroll
        for (int q = 0; q < 4; q++) atomicAdd(op + q, xp[q]);
    }
}

// ---------------- classifier ----------------
__global__ void dot_score(const float* __restrict__ xu, const float* __restrict__ xs,
                          const int* __restrict__ ui, const int* __restrict__ si,
                          float* __restrict__ out, int E)
{
    int gid = blockIdx.x * blockDim.x + threadIdx.x;
    int e = gid >> 4;
    int j = (gid & 15) << 2;
    int ec = (e < E) ? e : (E - 1);
    float4 a = *(const float4*)(xu + (size_t)ui[ec] * CC + j);
    float4 b = *(const float4*)(xs + (size_t)si[ec] * CC + j);
    float d = a.x*b.x + a.y*b.y + a.z*b.z + a.w*b.w;
    d += __shfl_xor_sync(0xffffffffu, d, 1);
    d += __shfl_xor_sync(0xffffffffu, d, 2);
    d += __shfl_xor_sync(0xffffffffu, d, 4);
    d += __shfl_xor_sync(0xffffffffu, d, 8);
    if ((gid & 15) == 0 && e < E) out[e] = d;
}

static inline int cdiv(int a, int b) { return (a + b - 1) / b; }

extern "C" void kernel_launch(void* const* d_in, const int* in_sizes, int n_in,
                              void* d_out, int out_size)
{
    const float* reviews  = (const float*)d_in[0];
    const float* overview = (const float*)d_in[1];
    const float* g_emb    = (const float*)d_in[2];
    const float* w_emb    = (const float*)d_in[3];
    const float* t_emb    = (const float*)d_in[4];
    const float* Wu  = (const float*)d_in[5];
    const float* bu  = (const float*)d_in[6];
    const float* Wsw = (const float*)d_in[7];
    const float* bs  = (const float*)d_in[8];
    const float* Wl1 = (const float*)d_in[9];
    const float* bl1 = (const float*)d_in[10];
    const float* Wr1 = (const float*)d_in[11];
    const float* Wl2 = (const float*)d_in[12];
    const float* bl2 = (const float*)d_in[13];
    const float* Wr2 = (const float*)d_in[14];
    const int* e_u2s = (const int*)d_in[15];
    const int* e_g2s = (const int*)d_in[16];
    const int* e_w2s = (const int*)d_in[17];
    const int* e_t2s = (const int*)d_in[18];
    const int* eli   = (const int*)d_in[19];
    float* out = (float*)d_out;

    float *deg,*agg,*xu,*xs,*yu,*ys,*xg,*xw,*xt,*xu2,*xs2;
    float *tS,*tW,*tG,*tT,*tS2,*tW2,*tG2,*tT2,*WrS1,*blS1,*WrS2,*blS2;
    cudaGetSymbolAddress((void**)&deg,  g_deg);
    cudaGetSymbolAddress((void**)&agg,  g_agg);
    cudaGetSymbolAddress((void**)&xu,   g_xu);
    cudaGetSymbolAddress((void**)&xs,   g_xs);
    cudaGetSymbolAddress((void**)&yu,   g_yu);
    cudaGetSymbolAddress((void**)&ys,   g_ys);
    cudaGetSymbolAddress((void**)&xg,   g_xg);
    cudaGetSymbolAddress((void**)&xw,   g_xw);
    cudaGetSymbolAddress((void**)&xt,   g_xt);
    cudaGetSymbolAddress((void**)&xu2,  g_xu2);
    cudaGetSymbolAddress((void**)&xs2,  g_xs2);
    cudaGetSymbolAddress((void**)&tS,   g_tS);
    cudaGetSymbolAddress((void**)&tW,   g_tW);
    cudaGetSymbolAddress((void**)&tG,   g_tG);
    cudaGetSymbolAddress((void**)&tT,   g_tT);
    cudaGetSymbolAddress((void**)&tS2,  g_tS2);
    cudaGetSymbolAddress((void**)&tW2,  g_tW2);
    cudaGetSymbolAddress((void**)&tG2,  g_tG2);
    cudaGetSymbolAddress((void**)&tT2,  g_tT2);
    cudaGetSymbolAddress((void**)&WrS1, g_WrS1);
    cudaGetSymbolAddress((void**)&blS1, g_blS1);
    cudaGetSymbolAddress((void**)&WrS2, g_WrS2);
    cudaGetSymbolAddress((void**)&blS2, g_blS2);

    const int W44 = CC*CC;

    // ---- init ----
    cudaMemsetAsync(deg, 0, DEG_TOT * sizeof(float));
    cudaMemsetAsync(agg, 0, AGG_TOT * sizeof(float));

    // ---- phase 0: input transforms (K=384) + deg counting + weight sums, fused ----
    {
        GemmJobs P{};
        P.j[0] = { reviews,  Wu,  bu, nullptr, nullptr, xu, NU, 0 };
        P.j[1] = { overview, Wsw, bs, nullptr, nullptr, xs, NS, 0 };
        phase0_fused<<<dim3(cdiv(NU,128), 3), 256>>>(P, e_u2s, e_g2s, e_w2s, e_t2s,
                                                     deg, Wr1, bl1, Wr2, bl2);
    }

    // ---- wave A: all independent K=64 GEMMs for layer 1 ----
    {
        GemmJobs A{};
        A.j[0] = { xs,    WrS1,        blS1,       nullptr, nullptr, ys, NS, 0 };
        A.j[1] = { xs,    Wl1 + 1*W44, nullptr,    nullptr, nullptr, tS, NS, 0 };
        A.j[2] = { w_emb, Wl1 + 4*W44, nullptr,    nullptr, nullptr, tW, NW, 0 };
        A.j[3] = { w_emb, Wr1 + 5*W44, bl1 + 5*CC, nullptr, nullptr, xw, NW, 0 };
        A.j[4] = { g_emb, Wl1 + 2*W44, nullptr,    nullptr, nullptr, tG, NG, 0 };
        A.j[5] = { g_emb, Wr1 + 3*W44, bl1 + 3*CC, nullptr, nullptr, xg, NG, 0 };
        A.j[6] = { t_emb, Wl1 + 6*W44, nullptr,    nullptr, nullptr, tT, NT, 0 };
        A.j[7] = { t_emb, Wr1 + 7*W44, bl1 + 7*CC, nullptr, nullptr, xt, NT, 0 };
        gemm_mma<CC><<<dim3(cdiv(NS,128), 8), 256>>>(A);
    }

    // ---- scatter wave A (all 8 edge flows of layer 1) ----
    {
        ScatJobs S{};
        S.j[0] = { xu, e_u2s,        e_u2s + E_US, nullptr,      agg + AGG_S };
        S.j[1] = { tS, e_u2s + E_US, e_u2s,        deg + DEG_U,  agg + AGG_U };
        S.j[2] = { tG, e_g2s,        e_g2s + E_GS, deg + DEG_SG, ys };
        S.j[3] = { xs, e_g2s + E_GS, e_g2s,        nullptr,      agg + AGG_G };
        S.j[4] = { tW, e_w2s,        e_w2s + E_WS, deg + DEG_SW, ys };
        S.j[5] = { xs, e_w2s + E_WS, e_w2s,        nullptr,      agg + AGG_W };
        S.j[6] = { tT, e_t2s,        e_t2s + E_TS, deg + DEG_ST, ys };
        S.j[7] = { xs, e_t2s + E_TS, e_t2s,        nullptr,      agg + AGG_T };
        int o = 0;
        S.off[0]=o; o+=E_US; S.off[1]=o; o+=E_US; S.off[2]=o; o+=E_GS; S.off[3]=o; o+=E_GS;
        S.off[4]=o; o+=E_WS; S.off[5]=o; o+=E_WS; S.off[6]=o; o+=E_TS; S.off[7]=o; o+=E_TS;
        S.off[8]=o; S.n = 8;
        scatter_multi<<<cdiv(o*4,256),256>>>(S);
    }

    // ---- wave B: finalize layer 1 (accumulate + relu epilogues) ----
    {
        GemmJobs B{};
        B.j[0] = { agg + AGG_S, Wl1 + 0*W44, nullptr,    ys,          deg + DEG_SU, ys, NS, 1 };
        B.j[1] = { xu,          Wr1 + 1*W44, bl1 + 1*CC, agg + AGG_U, nullptr,      yu, NU, 1 };
        B.j[2] = { agg + AGG_G, Wl1 + 3*W44, nullptr,    xg,          deg + DEG_G,  xg, NG, 1 };
        B.j[3] = { agg + AGG_W, Wl1 + 5*W44, nullptr,    xw,          deg + DEG_W,  xw, NW, 1 };
        B.j[4] = { agg + AGG_T, Wl1 + 7*W44, nullptr,    xt,          deg + DEG_T,  xt, NT, 1 };
        gemm_mma<CC><<<dim3(cdiv(NU,128), 5), 256>>>(B);
    }

    // ---- wave C: layer 2 independent GEMMs ----
    {
        GemmJobs Cj{};
        Cj.j[0] = { ys, WrS2,        blS2,       nullptr, nullptr, xs2, NS, 0 };
        Cj.j[1] = { ys, Wl2 + 1*W44, nullptr,    nullptr, nullptr, tS2, NS, 0 };
        Cj.j[2] = { xw, Wl2 + 4*W44, nullptr,    nullptr, nullptr, tW2, NW, 0 };
        Cj.j[3] = { xg, Wl2 + 2*W44, nullptr,    nullptr, nullptr, tG2, NG, 0 };
        Cj.j[4] = { xt, Wl2 + 6*W44, nullptr,    nullptr, nullptr, tT2, NT, 0 };
        Cj.j[5] = { yu, Wr2 + 1*W44, bl2 + 1*CC, nullptr, nullptr, xu2, NU, 0 };
        gemm_mma<CC><<<dim3(cdiv(NU,128), 6), 256>>>(Cj);
    }

    // ---- re-zero series agg, scatter wave C ----
    cudaMemsetAsync(agg + AGG_S, 0, (size_t)NS * CC * sizeof(float));
    {
        ScatJobs S{};
        S.j[0] = { yu,  e_u2s,        e_u2s + E_US, nullptr,      agg + AGG_S };
        S.j[1] = { tS2, e_u2s + E_US, e_u2s,        deg + DEG_U,  xu2 };
        S.j[2] = { tG2, e_g2s,        e_g2s + E_GS, deg + DEG_SG, xs2 };
        S.j[3] = { tW2, e_w2s,        e_w2s + E_WS, deg + DEG_SW, xs2 };
        S.j[4] = { tT2, e_t2s,        e_t2s + E_TS, deg + DEG_ST, xs2 };
        int o = 0;
        S.off[0]=o; o+=E_US; S.off[1]=o; o+=E_US; S.off[2]=o; o+=E_GS;
        S.off[3]=o; o+=E_WS; S.off[4]=o; o+=E_TS; S.off[5]=o;
        S.n = 5;
        scatter_multi<<<cdiv(o*4,256),256>>>(S);
    }

    // ---- wave D: final series accumulate ----
    {
        GemmJobs D{};
        D.j[0] = { agg + AGG_S, Wl2 + 0*W44, nullptr, xs2, deg + DEG_SU, xs2, NS, 0 };
        gemm_mma<CC><<<dim3(cdiv(NS,128), 1), 256>>>(D);
    }

    // ---- classifier ----
    dot_score<<<E_LI*16/256,256>>>(xu2, xs2, eli, eli + E_LI, out, E_LI);
}

// round 4
// speedup vs baseline: 2.4720x; 1.4271x over previous
#include <cuda_runtime.h>
#include <cuda_bf16.h>
#include <cstdint>

#define NU 100000
#define NS 50000
#define NG 50
#define NW 20000
#define NT 10
#define CC 64
#define FF 384
#define E_US 1000000
#define E_GS 150000
#define E_WS 50000
#define E_TS 50000
#define E_LI 200000

// ---- concatenated degree buffer layout ----
#define DEG_U   0
#define DEG_SU  (NU)
#define DEG_SG  (NU+NS)
#define DEG_SW  (NU+2*NS)
#define DEG_ST  (NU+3*NS)
#define DEG_G   (NU+4*NS)
#define DEG_W   (NU+4*NS+NG)
#define DEG_T   (NU+4*NS+NG+NW)
#define DEG_TOT (NU+4*NS+NG+NW+NT)

// ---- small agg buffer (only genres/writer/type need post-aggregation) ----
#define AGG_G 0
#define AGG_W ((size_t)NG*CC)
#define AGG_T ((size_t)(NG+NW)*CC)
#define AGG_TOT ((size_t)(NG+NW+NT)*CC)

// ---------------- scratch (device globals; allocation-free) ----------------
__device__ float g_deg[DEG_TOT];
__device__ float g_agg[AGG_TOT];
__device__ float g_xu[NU*CC], g_xs[NS*CC];
__device__ float g_yu[NU*CC], g_ys[NS*CC];
__device__ float g_xg[NG*CC], g_xw[NW*CC], g_xt[NT*CC];
__device__ float g_xu2[NU*CC], g_xs2[NS*CC];
__device__ float g_tU[NU*CC], g_tS[NS*CC], g_tG[NG*CC], g_tW[NW*CC], g_tT[NT*CC];
__device__ float g_tU2[NU*CC], g_tS2[NS*CC], g_tG2[NG*CC], g_tW2[NW*CC], g_tT2[NT*CC];
__device__ float g_WrS1[CC*CC], g_blS1[CC], g_WrS2[CC*CC], g_blS2[CC];

// ---------------- bf16 split helpers ----------------
__device__ __forceinline__ void split2(float x, float y, uint32_t& hi, uint32_t& lo) {
    __nv_bfloat162 h = __floats2bfloat162_rn(x, y);
    float2 hf = __bfloat1622float2(h);
    __nv_bfloat162 l = __floats2bfloat162_rn(x - hf.x, y - hf.y);
    hi = *(uint32_t*)&h;
    lo = *(uint32_t*)&l;
}
__device__ __forceinline__ void mma16(float* d, const uint32_t* a, uint32_t b0, uint32_t b1) {
    asm("mma.sync.aligned.m16n8k16.row.col.f32.bf16.bf16.f32 "
        "{%0,%1,%2,%3}, {%4,%5,%6,%7}, {%8,%9}, {%0,%1,%2,%3};"
        : "+f"(d[0]), "+f"(d[1]), "+f"(d[2]), "+f"(d[3])
        : "r"(a[0]), "r"(a[1]), "r"(a[2]), "r"(a[3]), "r"(b0), "r"(b1));
}

// ---------------- single GEMM: out = f( scale(m)*(A@W^T) + bias + accin ) ----
struct GemmJob {
    const float* A; const float* W; const float* bias; const float* accin;
    const float* deg; float* out; int M; int relu;
};
struct GemmJobs { GemmJob j[8]; };

template<int KT>
__device__ __forceinline__ void gemm_body(const GemmJob& jb)
{
    const int m0 = blockIdx.x * 128;
    if (m0 >= jb.M) return;

    __shared__ uint32_t Whi[64][36];
    __shared__ uint32_t Wlo[64][36];

    const int tid = threadIdx.x, wid = tid >> 5, lane = tid & 31;
    const int g = lane >> 2, tg = lane & 3;

    float acc[8][4];
#pragma unroll
    for (int j = 0; j < 8; j++) { acc[j][0]=acc[j][1]=acc[j][2]=acc[j][3]=0.f; }

    const int mtop = jb.M - 1;
    const int mr0 = m0 + wid * 16 + g;
    const float* A0 = jb.A + (size_t)min(mr0,     mtop) * KT;
    const float* A1 = jb.A + (size_t)min(mr0 + 8, mtop) * KT;

    for (int k0 = 0; k0 < KT; k0 += 64) {
        if (k0) __syncthreads();
#pragma unroll
        for (int i = tid; i < 64 * 32; i += 256) {
            int n = i >> 5, kp = i & 31;
            float2 w = *(const float2*)(jb.W + (size_t)n * KT + k0 + 2 * kp);
            split2(w.x, w.y, Whi[n][kp], Wlo[n][kp]);
        }
        __syncthreads();
#pragma unroll
        for (int ks = 0; ks < 4; ks++) {
            const int kk = k0 + ks * 16 + 2 * tg;
            float2 a00 = *(const float2*)(A0 + kk);
            float2 a10 = *(const float2*)(A1 + kk);
            float2 a01 = *(const float2*)(A0 + kk + 8);
            float2 a11 = *(const float2*)(A1 + kk + 8);
            uint32_t ah[4], al[4];
            split2(a00.x, a00.y, ah[0], al[0]);
            split2(a10.x, a10.y, ah[1], al[1]);
            split2(a01.x, a01.y, ah[2], al[2]);
            split2(a11.x, a11.y, ah[3], al[3]);
#pragma unroll
            for (int j = 0; j < 8; j++) {
                uint32_t bh0 = Whi[j*8 + g][ks*8 + tg];
                uint32_t bh1 = Whi[j*8 + g][ks*8 + tg + 4];
                uint32_t bl0 = Wlo[j*8 + g][ks*8 + tg];
                uint32_t bl1 = Wlo[j*8 + g][ks*8 + tg + 4];
                mma16(acc[j], ah, bh0, bh1);
                mma16(acc[j], al, bh0, bh1);
                mma16(acc[j], ah, bl0, bl1);
            }
        }
    }

    const float s0 = jb.deg ? 1.f / fmaxf(jb.deg[min(mr0,     mtop)], 1.f) : 1.f;
    const float s1 = jb.deg ? 1.f / fmaxf(jb.deg[min(mr0 + 8, mtop)], 1.f) : 1.f;
#pragma unroll
    for (int j = 0; j < 8; j++) {
        const int n = j * 8 + 2 * tg;
        float bv0 = 0.f, bv1 = 0.f;
        if (jb.bias) { bv0 = jb.bias[n]; bv1 = jb.bias[n + 1]; }
        if (mr0 < jb.M) {
            float v0 = acc[j][0] * s0 + bv0;
            float v1 = acc[j][1] * s0 + bv1;
            if (jb.accin) {
                float2 c = *(const float2*)(jb.accin + (size_t)mr0 * CC + n);
                v0 += c.x; v1 += c.y;
            }
            if (jb.relu) { v0 = fmaxf(v0, 0.f); v1 = fmaxf(v1, 0.f); }
            *(float2*)(jb.out + (size_t)mr0 * CC + n) = make_float2(v0, v1);
        }
        if (mr0 + 8 < jb.M) {
            float v0 = acc[j][2] * s1 + bv0;
            float v1 = acc[j][3] * s1 + bv1;
            if (jb.accin) {
                float2 c = *(const float2*)(jb.accin + (size_t)(mr0 + 8) * CC + n);
                v0 += c.x; v1 += c.y;
            }
            if (jb.relu) { v0 = fmaxf(v0, 0.f); v1 = fmaxf(v1, 0.f); }
            *(float2*)(jb.out + (size_t)(mr0 + 8) * CC + n) = make_float2(v0, v1);
        }
    }
}

template<int KT>
__global__ void __launch_bounds__(256) gemm_mma(const GemmJobs jobs)
{
    gemm_body<KT>(jobs.j[blockIdx.y]);
}

// ---------------- dual GEMM (K=64): two weight sets, one A read ----------------
struct DualJob {
    const float* A; const float* W0; const float* b0; float* o0;
    const float* W1; const float* b1; float* o1; int M; int relu_in;
};
struct DualJobs { DualJob j[6]; };

__global__ void __launch_bounds__(256) gemm_dual(const DualJobs jobs)
{
    const DualJob jb = jobs.j[blockIdx.y];
    const int m0 = blockIdx.x * 128;
    if (m0 >= jb.M) return;

    __shared__ uint32_t Whi[2][64][36];
    __shared__ uint32_t Wlo[2][64][36];

    const int tid = threadIdx.x, wid = tid >> 5, lane = tid & 31;
    const int g = lane >> 2, tg = lane & 3;

    // stage both weight matrices
#pragma unroll
    for (int i = tid; i < 2 * 64 * 32; i += 256) {
        int w = i >> 11, rem = i & 2047;
        int n = rem >> 5, kp = rem & 31;
        const float* Wp = w ? jb.W1 : jb.W0;
        float2 v = *(const float2*)(Wp + (size_t)n * CC + 2 * kp);
        split2(v.x, v.y, Whi[w][n][kp], Wlo[w][n][kp]);
    }
    __syncthreads();

    float acc[2][8][4];
#pragma unroll
    for (int w = 0; w < 2; w++)
#pragma unroll
        for (int j = 0; j < 8; j++) { acc[w][j][0]=acc[w][j][1]=acc[w][j][2]=acc[w][j][3]=0.f; }

    const int mtop = jb.M - 1;
    const int mr0 = m0 + wid * 16 + g;
    const float* A0 = jb.A + (size_t)min(mr0,     mtop) * CC;
    const float* A1 = jb.A + (size_t)min(mr0 + 8, mtop) * CC;

#pragma unroll
    for (int ks = 0; ks < 4; ks++) {
        const int kk = ks * 16 + 2 * tg;
        float2 a00 = *(const float2*)(A0 + kk);
        float2 a10 = *(const float2*)(A1 + kk);
        float2 a01 = *(const float2*)(A0 + kk + 8);
        float2 a11 = *(const float2*)(A1 + kk + 8);
        if (jb.relu_in) {
            a00.x=fmaxf(a00.x,0.f); a00.y=fmaxf(a00.y,0.f);
            a10.x=fmaxf(a10.x,0.f); a10.y=fmaxf(a10.y,0.f);
            a01.x=fmaxf(a01.x,0.f); a01.y=fmaxf(a01.y,0.f);
            a11.x=fmaxf(a11.x,0.f); a11.y=fmaxf(a11.y,0.f);
        }
        uint32_t ah[4], al[4];
        split2(a00.x, a00.y, ah[0], al[0]);
        split2(a10.x, a10.y, ah[1], al[1]);
        split2(a01.x, a01.y, ah[2], al[2]);
        split2(a11.x, a11.y, ah[3], al[3]);
#pragma unroll
        for (int w = 0; w < 2; w++) {
#pragma unroll
            for (int j = 0; j < 8; j++) {
                uint32_t bh0 = Whi[w][j*8 + g][ks*8 + tg];
                uint32_t bh1 = Whi[w][j*8 + g][ks*8 + tg + 4];
                uint32_t bl0 = Wlo[w][j*8 + g][ks*8 + tg];
                uint32_t bl1 = Wlo[w][j*8 + g][ks*8 + tg + 4];
                mma16(acc[w][j], ah, bh0, bh1);
                mma16(acc[w][j], al, bh0, bh1);
                mma16(acc[w][j], ah, bl0, bl1);
            }
        }
    }

#pragma unroll
    for (int w = 0; w < 2; w++) {
        const float* bias = w ? jb.b1 : jb.b0;
        float* outp = w ? jb.o1 : jb.o0;
#pragma unroll
        for (int j = 0; j < 8; j++) {
            const int n = j * 8 + 2 * tg;
            float bv0 = 0.f, bv1 = 0.f;
            if (bias) { bv0 = bias[n]; bv1 = bias[n + 1]; }
            if (mr0 < jb.M)
                *(float2*)(outp + (size_t)mr0 * CC + n) =
                    make_float2(acc[w][j][0] + bv0, acc[w][j][1] + bv1);
            if (mr0 + 8 < jb.M)
                *(float2*)(outp + (size_t)(mr0 + 8) * CC + n) =
                    make_float2(acc[w][j][2] + bv0, acc[w][j][3] + bv1);
        }
    }
}

// phase0 + degree counting + weight sums fused
__global__ void __launch_bounds__(256) phase0_fused(
    const GemmJobs jobs,
    const int* __restrict__ u2s, const int* __restrict__ g2s,
    const int* __restrict__ w2s, const int* __restrict__ t2s,
    float* __restrict__ deg,
    const float* __restrict__ Wr1, const float* __restrict__ bl1,
    const float* __restrict__ Wr2, const float* __restrict__ bl2)
{
    if (blockIdx.y == 2) {
        const int stride = gridDim.x * 256;
        int base = blockIdx.x * 256 + threadIdx.x;
        for (int i = base; i < E_US; i += stride) {
            atomicAdd(deg + DEG_U  + u2s[i], 1.f);
            atomicAdd(deg + DEG_SU + u2s[E_US + i], 1.f);
        }
        for (int i = base; i < E_GS; i += stride) {
            atomicAdd(deg + DEG_G  + g2s[i], 1.f);
            atomicAdd(deg + DEG_SG + g2s[E_GS + i], 1.f);
        }
        for (int i = base; i < E_WS; i += stride) {
            atomicAdd(deg + DEG_W  + w2s[i], 1.f);
            atomicAdd(deg + DEG_SW + w2s[E_WS + i], 1.f);
        }
        for (int i = base; i < E_TS; i += stride) {
            atomicAdd(deg + DEG_T  + t2s[i], 1.f);
            atomicAdd(deg + DEG_ST + t2s[E_TS + i], 1.f);
        }
        if (blockIdx.x == 0) {
            for (int i = threadIdx.x; i < CC * CC; i += 256) {
                g_WrS1[i] = Wr1[i] + Wr1[2*CC*CC + i] + Wr1[4*CC*CC + i] + Wr1[6*CC*CC + i];
                g_WrS2[i] = Wr2[i] + Wr2[2*CC*CC + i] + Wr2[4*CC*CC + i] + Wr2[6*CC*CC + i];
            }
            if (threadIdx.x < CC) {
                int i = threadIdx.x;
                g_blS1[i] = bl1[i] + bl1[2*CC + i] + bl1[4*CC + i] + bl1[6*CC + i];
                g_blS2[i] = bl2[i] + bl2[2*CC + i] + bl2[4*CC + i] + bl2[6*CC + i];
            }
        }
        return;
    }
    gemm_body<FF>(jobs.j[blockIdx.y]);
}

// ---------------- batched scatter: out[dst] += x[src] * (scale? 1/max(deg[dst],1):1) ----
// 8 threads per edge, 2 float4 each
struct ScatJob { const float* x; const int* src; const int* dst; const float* scale; float* out; };
struct ScatJobs { ScatJob j[8]; int off[9]; int n; };

__global__ void __launch_bounds__(256) scatter_multi(const ScatJobs js)
{
    int gid = blockIdx.x * 256 + threadIdx.x;
    int ge = gid >> 3;
    if (ge >= js.off[js.n]) return;
    int part = gid & 7;
    int jj = 0;
    while (ge >= js.off[jj + 1]) jj++;
    const ScatJob jb = js.j[jj];
    int e = ge - js.off[jj];
    int s = jb.src[e], d = jb.dst[e];
    const float4* xp = (const float4*)(jb.x + (size_t)s * CC);
    float4*       op = (float4*)(jb.out + (size_t)d * CC);
    float4 v0 = xp[part], v1 = xp[part + 8];
    if (jb.scale) {
        float sc = 1.f / fmaxf(jb.scale[d], 1.f);
        v0.x *= sc; v0.y *= sc; v0.z *= sc; v0.w *= sc;
        v1.x *= sc; v1.y *= sc; v1.z *= sc; v1.w *= sc;
    }
    atomicAdd(op + part, v0);
    atomicAdd(op + part + 8, v1);
}

// ---------------- classifier ----------------
__global__ void dot_score(const float* __restrict__ xu, const float* __restrict__ xs,
                          const int* __restrict__ ui, const int* __restrict__ si,
                          float* __restrict__ out, int E)
{
    int gid = blockIdx.x * blockDim.x + threadIdx.x;
    int e = gid >> 4;
    int j = (gid & 15) << 2;
    int ec = (e < E) ? e : (E - 1);
    float4 a = *(const float4*)(xu + (size_t)ui[ec] * CC + j);
    float4 b = *(const float4*)(xs + (size_t)si[ec] * CC + j);
    float d = a.x*b.x + a.y*b.y + a.z*b.z + a.w*b.w;
    d += __shfl_xor_sync(0xffffffffu, d, 1);
    d += __shfl_xor_sync(0xffffffffu, d, 2);
    d += __shfl_xor_sync(0xffffffffu, d, 4);
    d += __shfl_xor_sync(0xffffffffu, d, 8);
    if ((gid & 15) == 0 && e < E) out[e] = d;
}

static inline int cdiv(int a, int b) { return (a + b - 1) / b; }

extern "C" void kernel_launch(void* const* d_in, const int* in_sizes, int n_in,
                              void* d_out, int out_size)
{
    const float* reviews  = (const float*)d_in[0];
    const float* overview = (const float*)d_in[1];
    const float* g_emb    = (const float*)d_in[2];
    const float* w_emb    = (const float*)d_in[3];
    const float* t_emb    = (const float*)d_in[4];
    const float* Wu  = (const float*)d_in[5];
    const float* bu  = (const float*)d_in[6];
    const float* Wsw = (const float*)d_in[7];
    const float* bs  = (const float*)d_in[8];
    const float* Wl1 = (const float*)d_in[9];
    const float* bl1 = (const float*)d_in[10];
    const float* Wr1 = (const float*)d_in[11];
    const float* Wl2 = (const float*)d_in[12];
    const float* bl2 = (const float*)d_in[13];
    const float* Wr2 = (const float*)d_in[14];
    const int* e_u2s = (const int*)d_in[15];
    const int* e_g2s = (const int*)d_in[16];
    const int* e_w2s = (const int*)d_in[17];
    const int* e_t2s = (const int*)d_in[18];
    const int* eli   = (const int*)d_in[19];
    float* out = (float*)d_out;

    float *deg,*agg,*xu,*xs,*yu,*ys,*xg,*xw,*xt,*xu2,*xs2;
    float *tU,*tS,*tG,*tW,*tT,*tU2,*tS2,*tG2,*tW2,*tT2,*WrS1,*blS1,*WrS2,*blS2;
    cudaGetSymbolAddress((void**)&deg,  g_deg);
    cudaGetSymbolAddress((void**)&agg,  g_agg);
    cudaGetSymbolAddress((void**)&xu,   g_xu);
    cudaGetSymbolAddress((void**)&xs,   g_xs);
    cudaGetSymbolAddress((void**)&yu,   g_yu);
    cudaGetSymbolAddress((void**)&ys,   g_ys);
    cudaGetSymbolAddress((void**)&xg,   g_xg);
    cudaGetSymbolAddress((void**)&xw,   g_xw);
    cudaGetSymbolAddress((void**)&xt,   g_xt);
    cudaGetSymbolAddress((void**)&xu2,  g_xu2);
    cudaGetSymbolAddress((void**)&xs2,  g_xs2);
    cudaGetSymbolAddress((void**)&tU,   g_tU);
    cudaGetSymbolAddress((void**)&tS,   g_tS);
    cudaGetSymbolAddress((void**)&tG,   g_tG);
    cudaGetSymbolAddress((void**)&tW,   g_tW);
    cudaGetSymbolAddress((void**)&tT,   g_tT);
    cudaGetSymbolAddress((void**)&tU2,  g_tU2);
    cudaGetSymbolAddress((void**)&tS2,  g_tS2);
    cudaGetSymbolAddress((void**)&tG2,  g_tG2);
    cudaGetSymbolAddress((void**)&tW2,  g_tW2);
    cudaGetSymbolAddress((void**)&tT2,  g_tT2);
    cudaGetSymbolAddress((void**)&WrS1, g_WrS1);
    cudaGetSymbolAddress((void**)&blS1, g_blS1);
    cudaGetSymbolAddress((void**)&WrS2, g_WrS2);
    cudaGetSymbolAddress((void**)&blS2, g_blS2);

    const int W44 = CC*CC;

    // ---- init ----
    cudaMemsetAsync(deg, 0, DEG_TOT * sizeof(float));
    cudaMemsetAsync(agg, 0, AGG_TOT * sizeof(float));

    // ---- phase 0: input transforms (K=384) + deg counting + weight sums ----
    {
        GemmJobs P{};
        P.j[0] = { reviews,  Wu,  bu, nullptr, nullptr, xu, NU, 0 };
        P.j[1] = { overview, Wsw, bs, nullptr, nullptr, xs, NS, 0 };
        phase0_fused<<<dim3(cdiv(NU,128), 3), 256>>>(P, e_u2s, e_g2s, e_w2s, e_t2s,
                                                     deg, Wr1, bl1, Wr2, bl2);
    }

    // ---- wave A: layer-1 self + pre-transforms (dual: one A read, two outputs) ----
    {
        DualJobs A{};
        A.j[0] = { xu,    Wl1 + 0*W44, nullptr, tU, Wr1 + 1*W44, bl1 + 1*CC, yu, NU, 0 };
        A.j[1] = { xs,    WrS1,        blS1,    ys, Wl1 + 1*W44, nullptr,    tS, NS, 0 };
        A.j[2] = { w_emb, Wl1 + 4*W44, nullptr, tW, Wr1 + 5*W44, bl1 + 5*CC, xw, NW, 0 };
        A.j[3] = { g_emb, Wl1 + 2*W44, nullptr, tG, Wr1 + 3*W44, bl1 + 3*CC, xg, NG, 0 };
        A.j[4] = { t_emb, Wl1 + 6*W44, nullptr, tT, Wr1 + 7*W44, bl1 + 7*CC, xt, NT, 0 };
        gemm_dual<<<dim3(cdiv(NU,128), 5), 256>>>(A);
    }

    // ---- scatter wave 1: scaled pre-transformed flows direct into outputs ----
    {
        ScatJobs S{};
        S.j[0] = { tU, e_u2s,        e_u2s + E_US, deg + DEG_SU, ys };          // u->s
        S.j[1] = { tS, e_u2s + E_US, e_u2s,        deg + DEG_U,  yu };          // s->u
        S.j[2] = { tG, e_g2s,        e_g2s + E_GS, deg + DEG_SG, ys };          // g->s
        S.j[3] = { xs, e_g2s + E_GS, e_g2s,        nullptr,      agg + AGG_G }; // s->g post
        S.j[4] = { tW, e_w2s,        e_w2s + E_WS, deg + DEG_SW, ys };          // w->s
        S.j[5] = { xs, e_w2s + E_WS, e_w2s,        nullptr,      agg + AGG_W }; // s->w post
        S.j[6] = { tT, e_t2s,        e_t2s + E_TS, deg + DEG_ST, ys };          // t->s
        S.j[7] = { xs, e_t2s + E_TS, e_t2s,        nullptr,      agg + AGG_T }; // s->t post
        int o = 0;
        S.off[0]=o; o+=E_US; S.off[1]=o; o+=E_US; S.off[2]=o; o+=E_GS; S.off[3]=o; o+=E_GS;
        S.off[4]=o; o+=E_WS; S.off[5]=o; o+=E_WS; S.off[6]=o; o+=E_TS; S.off[7]=o; o+=E_TS;
        S.off[8]=o; S.n = 8;
        scatter_multi<<<cdiv(o*8,256),256>>>(S);
    }

    // ---- wave B: finalize small node types (post agg + accumulate + relu) ----
    {
        GemmJobs B{};
        B.j[0] = { agg + AGG_W, Wl1 + 5*W44, nullptr, xw, deg + DEG_W, xw, NW, 1 };
        B.j[1] = { agg + AGG_G, Wl1 + 3*W44, nullptr, xg, deg + DEG_G, xg, NG, 1 };
        B.j[2] = { agg + AGG_T, Wl1 + 7*W44, nullptr, xt, deg + DEG_T, xt, NT, 1 };
        gemm_mma<CC><<<dim3(cdiv(NW,128), 3), 256>>>(B);
    }

    // ---- wave C: layer-2 GEMMs (relu applied at A-load for ys/yu) ----
    {
        GemmJobs Cs{};
        Cs.j[0] = { xw, Wl2 + 4*W44, nullptr, nullptr, nullptr, tW2, NW, 0 };
        Cs.j[1] = { xg, Wl2 + 2*W44, nullptr, nullptr, nullptr, tG2, NG, 0 };
        Cs.j[2] = { xt, Wl2 + 6*W44, nullptr, nullptr, nullptr, tT2, NT, 0 };
        gemm_mma<CC><<<dim3(cdiv(NW,128), 3), 256>>>(Cs);

        DualJobs Cd{};
        Cd.j[0] = { yu, Wl2 + 0*W44, nullptr, tU2, Wr2 + 1*W44, bl2 + 1*CC, xu2, NU, 1 };
        Cd.j[1] = { ys, WrS2,        blS2,    xs2, Wl2 + 1*W44, nullptr,    tS2, NS, 1 };
        gemm_dual<<<dim3(cdiv(NU,128), 2), 256>>>(Cd);
    }

    // ---- scatter wave 2: direct scaled scatter into layer-2 outputs ----
    {
        ScatJobs S{};
        S.j[0] = { tU2, e_u2s,        e_u2s + E_US, deg + DEG_SU, xs2 };
        S.j[1] = { tS2, e_u2s + E_US, e_u2s,        deg + DEG_U,  xu2 };
        S.j[2] = { tG2, e_g2s,        e_g2s + E_GS, deg + DEG_SG, xs2 };
        S.j[3] = { tW2, e_w2s,        e_w2s + E_WS, deg + DEG_SW, xs2 };
        S.j[4] = { tT2, e_t2s,        e_t2s + E_TS, deg + DEG_ST, xs2 };
        int o = 0;
        S.off[0]=o; o+=E_US; S.off[1]=o; o+=E_US; S.off[2]=o; o+=E_GS;
        S.off[3]=o; o+=E_WS; S.off[4]=o; o+=E_TS; S.off[5]=o;
        S.n = 5;
        scatter_multi<<<cdiv(o*8,256),256>>>(S);
    }

    // ---- classifier ----
    dot_score<<<E_LI*16/256,256>>>(xu2, xs2, eli, eli + E_LI, out, E_LI);
}

// round 5
// speedup vs baseline: 2.6033x; 1.0531x over previous
#include <cuda_runtime.h>
#include <cuda_bf16.h>
#include <cstdint>

#define NU 100000
#define NS 50000
#define NG 50
#define NW 20000
#define NT 10
#define CC 64
#define FF 384
#define E_US 1000000
#define E_GS 150000
#define E_WS 50000
#define E_TS 50000
#define E_LI 200000

// ---- int degree/count layout (first N_SCAN entries get scanned into CSR offsets) ----
#define CNT_U   0
#define CNT_SU  (NU)
#define CNT_SG  (NU+NS)
#define CNT_SW  (NU+2*NS)
#define CNT_ST  (NU+3*NS)
#define CNT_G   (NU+4*NS)
#define CNT_W   (NU+4*NS+NG)
#define CNT_T   (NU+4*NS+NG+NW)
#define CNT_TOT (NU+4*NS+NG+NW+NT)

#define N_SCAN  (NU + 4*NS)                       // 300000
#define CSR_TOT (2*E_US + E_GS + E_WS + E_TS)     // 2250000
#define CHUNK   1024
#define NCHUNK  ((N_SCAN + CHUNK - 1) / CHUNK)    // 293

// ---- small agg buffer (only s->g/w/t reverse flows need post-aggregation) ----
#define AGG_G 0
#define AGG_W ((size_t)NG*CC)
#define AGG_T ((size_t)(NG+NW)*CC)
#define AGG_TOT ((size_t)(NG+NW+NT)*CC)

// ---------------- scratch (device globals; allocation-free) ----------------
__device__ int   g_cnt[CNT_TOT];
__device__ int   g_cur[N_SCAN];
__device__ int   g_off[N_SCAN + 1];
__device__ int   g_csum[NCHUNK], g_cbase[NCHUNK];
__device__ int   g_csr[CSR_TOT];
__device__ float g_agg[AGG_TOT];

__device__ float g_xs[NS*CC];                    // raw series transform (for s->g/w/t)
__device__ float g_yu[NU*CC], g_ys[NS*CC];       // layer-1 outputs (pre + gathered)
__device__ float g_xu2[NU*CC], g_xs2[NS*CC];     // layer-2 outputs
__device__ float g_tU[NU*CC], g_tS[NS*CC], g_tG[NG*CC], g_tW[NW*CC], g_tT[NT*CC];
__device__ float g_tU2[NU*CC], g_tS2[NS*CC], g_tG2[NG*CC], g_tW2[NW*CC], g_tT2[NT*CC];
__device__ float g_xwp[NW*CC], g_xgp[NG*CC], g_xtp[NT*CC];  // layer-1 self pre-terms
__device__ float g_WrS1[CC*CC], g_blS1[CC], g_WrS2[CC*CC], g_blS2[CC];

// ---------------- bf16 split helpers ----------------
__device__ __forceinline__ void split2(float x, float y, uint32_t& hi, uint32_t& lo) {
    __nv_bfloat162 h = __floats2bfloat162_rn(x, y);
    float2 hf = __bfloat1622float2(h);
    __nv_bfloat162 l = __floats2bfloat162_rn(x - hf.x, y - hf.y);
    hi = *(uint32_t*)&h;
    lo = *(uint32_t*)&l;
}
__device__ __forceinline__ void mma16(float* d, const uint32_t* a, uint32_t b0, uint32_t b1) {
    asm("mma.sync.aligned.m16n8k16.row.col.f32.bf16.bf16.f32 "
        "{%0,%1,%2,%3}, {%4,%5,%6,%7}, {%8,%9}, {%0,%1,%2,%3};"
        : "+f"(d[0]), "+f"(d[1]), "+f"(d[2]), "+f"(d[3])
        : "r"(a[0]), "r"(a[1]), "r"(a[2]), "r"(a[3]), "r"(b0), "r"(b1));
}

// stage a 64x64 weight matrix (row stride `ld`) into shared as bf16 hi/lo pairs
__device__ __forceinline__ void stage_w(const float* W, int ld, int k0,
                                        uint32_t (*Whi)[36], uint32_t (*Wlo)[36], int tid) {
#pragma unroll
    for (int i = tid; i < 64 * 32; i += 256) {
        int n = i >> 5, kp = i & 31;
        float2 w = *(const float2*)(W + (size_t)n * ld + k0 + 2 * kp);
        split2(w.x, w.y, Whi[n][kp], Wlo[n][kp]);
    }
}

__device__ __forceinline__ void mma_shared(float (*acc)[4], const uint32_t* ah, const uint32_t* al,
                                           const uint32_t (*Whi)[36], const uint32_t (*Wlo)[36],
                                           int ks, int g, int tg) {
#pragma unroll
    for (int j = 0; j < 8; j++) {
        uint32_t bh0 = Whi[j*8+g][ks*8+tg], bh1 = Whi[j*8+g][ks*8+tg+4];
        uint32_t bl0 = Wlo[j*8+g][ks*8+tg], bl1 = Wlo[j*8+g][ks*8+tg+4];
        mma16(acc[j], ah, bh0, bh1);
        mma16(acc[j], al, bh0, bh1);
        mma16(acc[j], ah, bl0, bl1);
    }
}

__device__ __forceinline__ void load_afrag(const float* A0, const float* A1, int kk, int relu,
                                           uint32_t* ah, uint32_t* al) {
    float2 a00 = *(const float2*)(A0 + kk);
    float2 a10 = *(const float2*)(A1 + kk);
    float2 a01 = *(const float2*)(A0 + kk + 8);
    float2 a11 = *(const float2*)(A1 + kk + 8);
    if (relu) {
        a00.x=fmaxf(a00.x,0.f); a00.y=fmaxf(a00.y,0.f);
        a10.x=fmaxf(a10.x,0.f); a10.y=fmaxf(a10.y,0.f);
        a01.x=fmaxf(a01.x,0.f); a01.y=fmaxf(a01.y,0.f);
        a11.x=fmaxf(a11.x,0.f); a11.y=fmaxf(a11.y,0.f);
    }
    split2(a00.x, a00.y, ah[0], al[0]);
    split2(a10.x, a10.y, ah[1], al[1]);
    split2(a01.x, a01.y, ah[2], al[2]);
    split2(a11.x, a11.y, ah[3], al[3]);
}

// chain: C-frags e[8][4] become A-frags of the next mma; weights read direct (L1-resident)
__device__ __forceinline__ void chain_dual(const float (*e)[4],
                                           const float* Wc0, const float* Wc1,
                                           float (*a2a)[4], float (*a2b)[4], int g, int tg) {
#pragma unroll
    for (int jj = 0; jj < 4; jj++) {
        uint32_t ah[4], al[4];
        split2(e[2*jj][0],   e[2*jj][1],   ah[0], al[0]);
        split2(e[2*jj][2],   e[2*jj][3],   ah[1], al[1]);
        split2(e[2*jj+1][0], e[2*jj+1][1], ah[2], al[2]);
        split2(e[2*jj+1][2], e[2*jj+1][3], ah[3], al[3]);
#pragma unroll
        for (int j = 0; j < 8; j++) {
            const float* wp0 = Wc0 + (size_t)(j*8+g)*CC + 16*jj + 2*tg;
            float2 w0 = *(const float2*)(wp0);
            float2 w1 = *(const float2*)(wp0 + 8);
            uint32_t bh0,bl0,bh1,bl1;
            split2(w0.x, w0.y, bh0, bl0);
            split2(w1.x, w1.y, bh1, bl1);
            mma16(a2a[j], ah, bh0, bh1);
            mma16(a2a[j], al, bh0, bh1);
            mma16(a2a[j], ah, bl0, bl1);
            if (Wc1) {
                const float* wp1 = Wc1 + (size_t)(j*8+g)*CC + 16*jj + 2*tg;
                float2 v0 = *(const float2*)(wp1);
                float2 v1 = *(const float2*)(wp1 + 8);
                split2(v0.x, v0.y, bh0, bl0);
                split2(v1.x, v1.y, bh1, bl1);
                mma16(a2b[j], ah, bh0, bh1);
                mma16(a2b[j], al, bh0, bh1);
                mma16(a2b[j], ah, bl0, bl1);
            }
        }
    }
}

__device__ __forceinline__ void store_frag(const float (*acc)[4], const float* bias,
                                           float* out, int mr0, int M, int tg) {
#pragma unroll
    for (int j = 0; j < 8; j++) {
        int n = j*8 + 2*tg;
        float b0 = bias ? bias[n] : 0.f, b1 = bias ? bias[n+1] : 0.f;
        if (mr0 < M)
            *(float2*)(out + (size_t)mr0*CC + n) = make_float2(acc[j][0]+b0, acc[j][1]+b1);
        if (mr0+8 < M)
            *(float2*)(out + (size_t)(mr0+8)*CC + n) = make_float2(acc[j][2]+b0, acc[j][3]+b1);
    }
}

// ---------------- prep: summed series self weights/biases ----------------
__global__ void prep(const float* __restrict__ Wr1, const float* __restrict__ bl1,
                     const float* __restrict__ Wr2, const float* __restrict__ bl2) {
    int i = blockIdx.x * 256 + threadIdx.x;
    if (i < CC*CC) {
        g_WrS1[i] = Wr1[i] + Wr1[2*CC*CC+i] + Wr1[4*CC*CC+i] + Wr1[6*CC*CC+i];
        g_WrS2[i] = Wr2[i] + Wr2[2*CC*CC+i] + Wr2[4*CC*CC+i] + Wr2[6*CC*CC+i];
    }
    if (i < CC) {
        g_blS1[i] = bl1[i] + bl1[2*CC+i] + bl1[4*CC+i] + bl1[6*CC+i];
        g_blS2[i] = bl2[i] + bl2[2*CC+i] + bl2[4*CC+i] + bl2[6*CC+i];
    }
}

// ---------------- phase0 mega: K=384 GEMM + dual register-chain + deg counting ----
struct P0Job {
    const float* A; const float* W; const float* bias; float* xout;
    const float* Wc0; const float* bc0; float* oc0;
    const float* Wc1; float* oc1;
    int M;
};

__global__ void __launch_bounds__(256) p0_mega(
    const P0Job j0, const P0Job j1,
    const int* __restrict__ u2s, const int* __restrict__ g2s,
    const int* __restrict__ w2s, const int* __restrict__ t2s,
    int* __restrict__ cnt)
{
    if (blockIdx.y == 2) {
        const int stride = gridDim.x * 256;
        int base = blockIdx.x * 256 + threadIdx.x;
        for (int i = base; i < E_US; i += stride) {
            atomicAdd(cnt + CNT_U  + u2s[i], 1);
            atomicAdd(cnt + CNT_SU + u2s[E_US + i], 1);
        }
        for (int i = base; i < E_GS; i += stride) {
            atomicAdd(cnt + CNT_G  + g2s[i], 1);
            atomicAdd(cnt + CNT_SG + g2s[E_GS + i], 1);
        }
        for (int i = base; i < E_WS; i += stride) {
            atomicAdd(cnt + CNT_W  + w2s[i], 1);
            atomicAdd(cnt + CNT_SW + w2s[E_WS + i], 1);
        }
        for (int i = base; i < E_TS; i += stride) {
            atomicAdd(cnt + CNT_T  + t2s[i], 1);
            atomicAdd(cnt + CNT_ST + t2s[E_TS + i], 1);
        }
        return;
    }
    const P0Job jb = blockIdx.y ? j1 : j0;
    const int m0 = blockIdx.x * 128;
    if (m0 >= jb.M) return;

    __shared__ uint32_t Whi[64][36], Wlo[64][36];
    const int tid = threadIdx.x, wid = tid >> 5, lane = tid & 31;
    const int g = lane >> 2, tg = lane & 3;

    float acc1[8][4];
#pragma unroll
    for (int j = 0; j < 8; j++) { acc1[j][0]=acc1[j][1]=acc1[j][2]=acc1[j][3]=0.f; }

    const int mtop = jb.M - 1;
    const int mr0 = m0 + wid * 16 + g;
    const float* A0 = jb.A + (size_t)min(mr0,     mtop) * FF;
    const float* A1 = jb.A + (size_t)min(mr0 + 8, mtop) * FF;

    for (int k0 = 0; k0 < FF; k0 += 64) {
        if (k0) __syncthreads();
        stage_w(jb.W, FF, k0, Whi, Wlo, tid);
        __syncthreads();
#pragma unroll
        for (int ks = 0; ks < 4; ks++) {
            uint32_t ah[4], al[4];
            load_afrag(A0, A1, k0 + ks*16 + 2*tg, 0, ah, al);
            mma_shared(acc1, ah, al, Whi, Wlo, ks, g, tg);
        }
    }

    // epilogue: add input bias in place -> acc1 is now x (xu or xs)
#pragma unroll
    for (int j = 0; j < 8; j++) {
        int n = j*8 + 2*tg;
        float b0 = jb.bias[n], b1 = jb.bias[n+1];
        acc1[j][0] += b0; acc1[j][1] += b1;
        acc1[j][2] += b0; acc1[j][3] += b1;
    }
    if (jb.xout) store_frag(acc1, nullptr, jb.xout, mr0, jb.M, tg);

    float a2a[8][4], a2b[8][4];
#pragma unroll
    for (int j = 0; j < 8; j++) {
        a2a[j][0]=a2a[j][1]=a2a[j][2]=a2a[j][3]=0.f;
        a2b[j][0]=a2b[j][1]=a2b[j][2]=a2b[j][3]=0.f;
    }
    chain_dual(acc1, jb.Wc0, jb.Wc1, a2a, a2b, g, tg);
    store_frag(a2a, jb.bc0, jb.oc0, mr0, jb.M, tg);
    store_frag(a2b, nullptr, jb.oc1, mr0, jb.M, tg);
}

// ---------------- scan (3 kernels) ----------------
__global__ void scan1(const int* __restrict__ cnt, int* __restrict__ csum) {
    __shared__ int sh[8];
    int c = blockIdx.x, t = threadIdx.x, base = c * CHUNK;
    int s = 0;
#pragma unroll
    for (int q = 0; q < 4; q++) {
        int idx = base + t*4 + q;
        if (idx < N_SCAN) s += cnt[idx];
    }
    for (int o = 16; o; o >>= 1) s += __shfl_down_sync(~0u, s, o);
    if ((t & 31) == 0) sh[t >> 5] = s;
    __syncthreads();
    if (t == 0) { int tot = 0; for (int w = 0; w < 8; w++) tot += sh[w]; csum[c] = tot; }
}
__global__ void scan2(const int* __restrict__ csum, int* __restrict__ cbase) {
    __shared__ int sh[512];
    int t = threadIdx.x;
    int v = (t < NCHUNK) ? csum[t] : 0;
    sh[t] = v; __syncthreads();
    for (int o = 1; o < 512; o <<= 1) {
        int x = (t >= o) ? sh[t - o] : 0;
        __syncthreads();
        sh[t] += x;
        __syncthreads();
    }
    if (t < NCHUNK) cbase[t] = sh[t] - v;
}
__global__ void scan3(const int* __restrict__ cnt, const int* __restrict__ cbase,
                      int* __restrict__ off) {
    __shared__ int sh[8];
    int c = blockIdx.x, t = threadIdx.x, base = c * CHUNK;
    int lane = t & 31, w = t >> 5;
    int v[4]; int s = 0;
#pragma unroll
    for (int q = 0; q < 4; q++) {
        int idx = base + t*4 + q;
        v[q] = (idx < N_SCAN) ? cnt[idx] : 0;
        s += v[q];
    }
    int incl = s;
    for (int o = 1; o < 32; o <<= 1) {
        int x = __shfl_up_sync(~0u, incl, o);
        if (lane >= o) incl += x;
    }
    if (lane == 31) sh[w] = incl;
    __syncthreads();
    if (t == 0) { int a = 0; for (int i = 0; i < 8; i++) { int x = sh[i]; sh[i] = a; a += x; } }
    __syncthreads();
    int excl = incl - s + sh[w] + cbase[c];
#pragma unroll
    for (int q = 0; q < 4; q++) {
        int idx = base + t*4 + q;
        if (idx < N_SCAN) off[idx] = excl;
        excl += v[q];
        if (idx == N_SCAN - 1) off[N_SCAN] = excl;
    }
}

// ---------------- CSR fill ----------------
__global__ void fill_csr(const int* __restrict__ u2s, const int* __restrict__ g2s,
                         const int* __restrict__ w2s, const int* __restrict__ t2s,
                         const int* __restrict__ off, int* __restrict__ cur,
                         int* __restrict__ csr) {
    int i = blockIdx.x * 256 + threadIdx.x;
    if (i < E_US) {
        int u = u2s[i], s = u2s[E_US + i];
        int n0 = CNT_SU + s;
        csr[off[n0] + atomicAdd(cur + n0, 1)] = u;
        int n1 = CNT_U + u;
        csr[off[n1] + atomicAdd(cur + n1, 1)] = s;
    }
    if (i < E_GS) {
        int gg = g2s[i], s = g2s[E_GS + i];
        int n = CNT_SG + s;
        csr[off[n] + atomicAdd(cur + n, 1)] = gg;
    }
    if (i < E_WS) {
        int ww = w2s[i], s = w2s[E_WS + i];
        int n = CNT_SW + s;
        csr[off[n] + atomicAdd(cur + n, 1)] = ww;
    }
    if (i < E_TS) {
        int tt = t2s[i], s = t2s[E_TS + i];
        int n = CNT_ST + s;
        csr[off[n] + atomicAdd(cur + n, 1)] = tt;
    }
}

// ---------------- dual GEMM (K=64): two weight sets, one A read ----------------
struct DualJob {
    const float* A; const float* W0; const float* b0; float* o0;
    const float* W1; const float* b1; float* o1; int M; int relu_in;
};
struct DualJobs { DualJob j[6]; };

__global__ void __launch_bounds__(256) gemm_dual(const DualJobs jobs) {
    const DualJob jb = jobs.j[blockIdx.y];
    const int m0 = blockIdx.x * 128;
    if (m0 >= jb.M) return;

    __shared__ uint32_t Whi[2][64][36];
    __shared__ uint32_t Wlo[2][64][36];
    const int tid = threadIdx.x, wid = tid >> 5, lane = tid & 31;
    const int g = lane >> 2, tg = lane & 3;

    stage_w(jb.W0, CC, 0, Whi[0], Wlo[0], tid);
    stage_w(jb.W1, CC, 0, Whi[1], Wlo[1], tid);
    __syncthreads();

    float acc[2][8][4];
#pragma unroll
    for (int w = 0; w < 2; w++)
#pragma unroll
        for (int j = 0; j < 8; j++) { acc[w][j][0]=acc[w][j][1]=acc[w][j][2]=acc[w][j][3]=0.f; }

    const int mtop = jb.M - 1;
    const int mr0 = m0 + wid * 16 + g;
    const float* A0 = jb.A + (size_t)min(mr0,     mtop) * CC;
    const float* A1 = jb.A + (size_t)min(mr0 + 8, mtop) * CC;

#pragma unroll
    for (int ks = 0; ks < 4; ks++) {
        uint32_t ah[4], al[4];
        load_afrag(A0, A1, ks*16 + 2*tg, jb.relu_in, ah, al);
        mma_shared(acc[0], ah, al, Whi[0], Wlo[0], ks, g, tg);
        mma_shared(acc[1], ah, al, Whi[1], Wlo[1], ks, g, tg);
    }
    store_frag(acc[0], jb.b0, jb.o0, mr0, jb.M, tg);
    store_frag(acc[1], jb.b1, jb.o1, mr0, jb.M, tg);
}

// ---------------- fused layer1-finalize + layer2 pre-transform (chain) ----------------
struct FBJob {
    const float* A; const float* W1; const float* accin; const int* cnt;
    const float* Wc; float* out; int M;
};
struct FBJobs { FBJob j[3]; };

__global__ void __launch_bounds__(256) fusedB_chain(const FBJobs jobs) {
    const FBJob jb = jobs.j[blockIdx.y];
    const int m0 = blockIdx.x * 128;
    if (m0 >= jb.M) return;

    __shared__ uint32_t Whi[64][36], Wlo[64][36];
    const int tid = threadIdx.x, wid = tid >> 5, lane = tid & 31;
    const int g = lane >> 2, tg = lane & 3;

    stage_w(jb.W1, CC, 0, Whi, Wlo, tid);
    __syncthreads();

    float acc1[8][4];
#pragma unroll
    for (int j = 0; j < 8; j++) { acc1[j][0]=acc1[j][1]=acc1[j][2]=acc1[j][3]=0.f; }

    const int mtop = jb.M - 1;
    const int mr0 = m0 + wid * 16 + g;
    const int r0 = min(mr0, mtop), r1 = min(mr0 + 8, mtop);
    const float* A0 = jb.A + (size_t)r0 * CC;
    const float* A1 = jb.A + (size_t)r1 * CC;

#pragma unroll
    for (int ks = 0; ks < 4; ks++) {
        uint32_t ah[4], al[4];
        load_afrag(A0, A1, ks*16 + 2*tg, 0, ah, al);
        mma_shared(acc1, ah, al, Whi, Wlo, ks, g, tg);
    }

    const float s0 = 1.f / fmaxf((float)jb.cnt[r0], 1.f);
    const float s1 = 1.f / fmaxf((float)jb.cnt[r1], 1.f);
#pragma unroll
    for (int j = 0; j < 8; j++) {
        int n = j*8 + 2*tg;
        float2 c0 = *(const float2*)(jb.accin + (size_t)r0 * CC + n);
        float2 c1 = *(const float2*)(jb.accin + (size_t)r1 * CC + n);
        acc1[j][0] = fmaxf(acc1[j][0]*s0 + c0.x, 0.f);
        acc1[j][1] = fmaxf(acc1[j][1]*s0 + c0.y, 0.f);
        acc1[j][2] = fmaxf(acc1[j][2]*s1 + c1.x, 0.f);
        acc1[j][3] = fmaxf(acc1[j][3]*s1 + c1.y, 0.f);
    }

    float a2[8][4], dummy[1][4];
#pragma unroll
    for (int j = 0; j < 8; j++) { a2[j][0]=a2[j][1]=a2[j][2]=a2[j][3]=0.f; }
    chain_dual(acc1, jb.Wc, nullptr, a2, dummy, g, tg);
    store_frag(a2, nullptr, jb.out, mr0, jb.M, tg);
}

// ---------------- warp-per-node CSR gather (series: 4 flows, users: 1 flow) --------
__global__ void __launch_bounds__(256) gather_nodes(
    const float* __restrict__ tU, const float* __restrict__ tS,
    const float* __restrict__ tG, const float* __restrict__ tW, const float* __restrict__ tT,
    float* __restrict__ outS, float* __restrict__ outU,
    const int* __restrict__ off, const int* __restrict__ csr)
{
    int gw = (blockIdx.x * 256 + threadIdx.x) >> 5;
    int lane = threadIdx.x & 31;
    float sx = 0.f, sy = 0.f;
    float* o;
    if (gw < NS) {
        const int d = gw;
        const int node[4] = { CNT_SU + d, CNT_SG + d, CNT_SW + d, CNT_ST + d };
        const float* buf[4] = { tU, tG, tW, tT };
#pragma unroll
        for (int f = 0; f < 4; f++) {
            int b = off[node[f]], e = off[node[f] + 1];
            float fx = 0.f, fy = 0.f;
            int i = b;
            for (; i + 1 < e; i += 2) {
                int s0 = csr[i], s1 = csr[i+1];
                float2 v0 = *(const float2*)(buf[f] + (size_t)s0 * CC + 2*lane);
                float2 v1 = *(const float2*)(buf[f] + (size_t)s1 * CC + 2*lane);
                fx += v0.x + v1.x; fy += v0.y + v1.y;
            }
            if (i < e) {
                int s0 = csr[i];
                float2 v0 = *(const float2*)(buf[f] + (size_t)s0 * CC + 2*lane);
                fx += v0.x; fy += v0.y;
            }
            float inv = 1.f / fmaxf((float)(e - b), 1.f);
            sx += fx * inv; sy += fy * inv;
        }
        o = outS + (size_t)d * CC + 2*lane;
    } else if (gw < NS + NU) {
        const int d = gw - NS;
        int b = off[CNT_U + d], e = off[CNT_U + d + 1];
        float fx = 0.f, fy = 0.f;
        int i = b;
        for (; i + 1 < e; i += 2) {
            int s0 = csr[i], s1 = csr[i+1];
            float2 v0 = *(const float2*)(tS + (size_t)s0 * CC + 2*lane);
            float2 v1 = *(const float2*)(tS + (size_t)s1 * CC + 2*lane);
            fx += v0.x + v1.x; fy += v0.y + v1.y;
        }
        if (i < e) {
            int s0 = csr[i];
            float2 v0 = *(const float2*)(tS + (size_t)s0 * CC + 2*lane);
            fx += v0.x; fy += v0.y;
        }
        float inv = 1.f / fmaxf((float)(e - b), 1.f);
        sx = fx * inv; sy = fy * inv;
        o = outU + (size_t)d * CC + 2*lane;
    } else return;
    float2 c = *(const float2*)o;
    *(float2*)o = make_float2(c.x + sx, c.y + sy);
}

// ---------------- small atomic scatter (s->g/w/t) ----------------
struct ScatJob { const float* x; const int* src; const int* dst; float* out; };
struct ScatJobs { ScatJob j[3]; int off[4]; };

__global__ void __launch_bounds__(256) scatter_small(const ScatJobs js) {
    int gid = blockIdx.x * 256 + threadIdx.x;
    int ge = gid >> 3;
    if (ge >= js.off[3]) return;
    int part = gid & 7;
    int jj = (ge >= js.off[1]) + (ge >= js.off[2]);
    const ScatJob jb = js.j[jj];
    int e = ge - js.off[jj];
    int s = jb.src[e], d = jb.dst[e];
    const float4* xp = (const float4*)(jb.x + (size_t)s * CC);
    float4*       op = (float4*)(jb.out + (size_t)d * CC);
    atomicAdd(op + part,     xp[part]);
    atomicAdd(op + part + 8, xp[part + 8]);
}

// ---------------- classifier ----------------
__global__ void dot_score(const float* __restrict__ xu, const float* __restrict__ xs,
                          const int* __restrict__ ui, const int* __restrict__ si,
                          float* __restrict__ out, int E) {
    int gid = blockIdx.x * blockDim.x + threadIdx.x;
    int e = gid >> 4;
    int j = (gid & 15) << 2;
    int ec = (e < E) ? e : (E - 1);
    float4 a = *(const float4*)(xu + (size_t)ui[ec] * CC + j);
    float4 b = *(const float4*)(xs + (size_t)si[ec] * CC + j);
    float d = a.x*b.x + a.y*b.y + a.z*b.z + a.w*b.w;
    d += __shfl_xor_sync(0xffffffffu, d, 1);
    d += __shfl_xor_sync(0xffffffffu, d, 2);
    d += __shfl_xor_sync(0xffffffffu, d, 4);
    d += __shfl_xor_sync(0xffffffffu, d, 8);
    if ((gid & 15) == 0 && e < E) out[e] = d;
}

static inline int cdiv(int a, int b) { return (a + b - 1) / b; }

extern "C" void kernel_launch(void* const* d_in, const int* in_sizes, int n_in,
                              void* d_out, int out_size)
{
    const float* reviews  = (const float*)d_in[0];
    const float* overview = (const float*)d_in[1];
    const float* g_emb    = (const float*)d_in[2];
    const float* w_emb    = (const float*)d_in[3];
    const float* t_emb    = (const float*)d_in[4];
    const float* Wu  = (const float*)d_in[5];
    const float* bu  = (const float*)d_in[6];
    const float* Wsw = (const float*)d_in[7];
    const float* bs  = (const float*)d_in[8];
    const float* Wl1 = (const float*)d_in[9];
    const float* bl1 = (const float*)d_in[10];
    const float* Wr1 = (const float*)d_in[11];
    const float* Wl2 = (const float*)d_in[12];
    const float* bl2 = (const float*)d_in[13];
    const float* Wr2 = (const float*)d_in[14];
    const int* e_u2s = (const int*)d_in[15];
    const int* e_g2s = (const int*)d_in[16];
    const int* e_w2s = (const int*)d_in[17];
    const int* e_t2s = (const int*)d_in[18];
    const int* eli   = (const int*)d_in[19];
    float* out = (float*)d_out;

    int *cnt,*cur,*off,*csum,*cbase,*csr;
    float *agg,*xs,*yu,*ys,*xu2,*xs2;
    float *tU,*tS,*tG,*tW,*tT,*tU2,*tS2,*tG2,*tW2,*tT2,*xwp,*xgp,*xtp;
    float *WrS1,*blS1,*WrS2,*blS2;
    cudaGetSymbolAddress((void**)&cnt,  g_cnt);
    cudaGetSymbolAddress((void**)&cur,  g_cur);
    cudaGetSymbolAddress((void**)&off,  g_off);
    cudaGetSymbolAddress((void**)&csum, g_csum);
    cudaGetSymbolAddress((void**)&cbase,g_cbase);
    cudaGetSymbolAddress((void**)&csr,  g_csr);
    cudaGetSymbolAddress((void**)&agg,  g_agg);
    cudaGetSymbolAddress((void**)&xs,   g_xs);
    cudaGetSymbolAddress((void**)&yu,   g_yu);
    cudaGetSymbolAddress((void**)&ys,   g_ys);
    cudaGetSymbolAddress((void**)&xu2,  g_xu2);
    cudaGetSymbolAddress((void**)&xs2,  g_xs2);
    cudaGetSymbolAddress((void**)&tU,   g_tU);
    cudaGetSymbolAddress((void**)&tS,   g_tS);
    cudaGetSymbolAddress((void**)&tG,   g_tG);
    cudaGetSymbolAddress((void**)&tW,   g_tW);
    cudaGetSymbolAddress((void**)&tT,   g_tT);
    cudaGetSymbolAddress((void**)&tU2,  g_tU2);
    cudaGetSymbolAddress((void**)&tS2,  g_tS2);
    cudaGetSymbolAddress((void**)&tG2,  g_tG2);
    cudaGetSymbolAddress((void**)&tW2,  g_tW2);
    cudaGetSymbolAddress((void**)&tT2,  g_tT2);
    cudaGetSymbolAddress((void**)&xwp,  g_xwp);
    cudaGetSymbolAddress((void**)&xgp,  g_xgp);
    cudaGetSymbolAddress((void**)&xtp,  g_xtp);
    cudaGetSymbolAddress((void**)&WrS1, g_WrS1);
    cudaGetSymbolAddress((void**)&blS1, g_blS1);
    cudaGetSymbolAddress((void**)&WrS2, g_WrS2);
    cudaGetSymbolAddress((void**)&blS2, g_blS2);

    const int W44 = CC*CC;

    // ---- init ----
    cudaMemsetAsync(cnt, 0, CNT_TOT * sizeof(int));
    cudaMemsetAsync(cur, 0, N_SCAN * sizeof(int));
    cudaMemsetAsync(agg, 0, AGG_TOT * sizeof(float));
    prep<<<16, 256>>>(Wr1, bl1, Wr2, bl2);

    // ---- phase0: input transforms + register-chained layer-1 pre-terms + deg count ----
    {
        P0Job ju = { reviews,  Wu,  bu, nullptr,
                     Wr1 + 1*W44, bl1 + 1*CC, yu,     // yu_pre = xu@Wr1_1 + bl1_1
                     Wl1 + 0*W44, tU,                 // tU = xu@Wl1_0
                     NU };
        P0Job js = { overview, Wsw, bs, xs,
                     WrS1, blS1, ys,                  // ys_pre = xs@WrS1 + blS1
                     Wl1 + 1*W44, tS,                 // tS = xs@Wl1_1
                     NS };
        p0_mega<<<dim3(cdiv(NU,128), 3), 256>>>(ju, js, e_u2s, e_g2s, e_w2s, e_t2s, cnt);
    }

    // ---- CSR build ----
    scan1<<<NCHUNK, 256>>>(cnt, csum);
    scan2<<<1, 512>>>(csum, cbase);
    scan3<<<NCHUNK, 256>>>(cnt, cbase, off);
    fill_csr<<<cdiv(E_US,256), 256>>>(e_u2s, e_g2s, e_w2s, e_t2s, off, cur, csr);

    // ---- small embedding duals: messages + self pre-terms ----
    {
        DualJobs A{};
        A.j[0] = { w_emb, Wl1 + 4*W44, nullptr, tW, Wr1 + 5*W44, bl1 + 5*CC, xwp, NW, 0 };
        A.j[1] = { g_emb, Wl1 + 2*W44, nullptr, tG, Wr1 + 3*W44, bl1 + 3*CC, xgp, NG, 0 };
        A.j[2] = { t_emb, Wl1 + 6*W44, nullptr, tT, Wr1 + 7*W44, bl1 + 7*CC, xtp, NT, 0 };
        gemm_dual<<<dim3(cdiv(NW,128), 3), 256>>>(A);
    }

    // ---- s->g/w/t reverse flows (atomic, small) ----
    {
        ScatJobs S{};
        S.j[0] = { xs, e_g2s + E_GS, e_g2s, agg + AGG_G };
        S.j[1] = { xs, e_w2s + E_WS, e_w2s, agg + AGG_W };
        S.j[2] = { xs, e_t2s + E_TS, e_t2s, agg + AGG_T };
        S.off[0] = 0; S.off[1] = E_GS; S.off[2] = E_GS + E_WS; S.off[3] = E_GS + E_WS + E_TS;
        scatter_small<<<cdiv(S.off[3]*8, 256), 256>>>(S);
    }

    // ---- gather 1: ys += means of {tU,tG,tW,tT}; yu += mean of tS ----
    gather_nodes<<<cdiv((NS+NU)*32, 256), 256>>>(tU, tS, tG, tW, tT, ys, yu, off, csr);

    // ---- fused: xw = relu(aggW@Wl1/deg + xwp) chained -> tW2 = xw@Wl2 (g,w,t) ----
    {
        FBJobs F{};
        F.j[0] = { agg + AGG_W, Wl1 + 5*W44, xwp, cnt + CNT_W, Wl2 + 4*W44, tW2, NW };
        F.j[1] = { agg + AGG_G, Wl1 + 3*W44, xgp, cnt + CNT_G, Wl2 + 2*W44, tG2, NG };
        F.j[2] = { agg + AGG_T, Wl1 + 7*W44, xtp, cnt + CNT_T, Wl2 + 6*W44, tT2, NT };
        fusedB_chain<<<dim3(cdiv(NW,128), 3), 256>>>(F);
    }

    // ---- layer-2 duals from relu'd layer-1 outputs ----
    {
        DualJobs C{};
        C.j[0] = { yu, Wl2 + 0*W44, nullptr, tU2, Wr2 + 1*W44, bl2 + 1*CC, xu2, NU, 1 };
        C.j[1] = { ys, WrS2,        blS2,    xs2, Wl2 + 1*W44, nullptr,    tS2, NS, 1 };
        gemm_dual<<<dim3(cdiv(NU,128), 2), 256>>>(C);
    }

    // ---- gather 2: xs2 += means of {tU2,tG2,tW2,tT2}; xu2 += mean of tS2 ----
    gather_nodes<<<cdiv((NS+NU)*32, 256), 256>>>(tU2, tS2, tG2, tW2, tT2, xs2, xu2, off, csr);

    // ---- classifier ----
    dot_score<<<E_LI*16/256, 256>>>(xu2, xs2, eli, eli + E_LI, out, E_LI);
}

// round 6
// speedup vs baseline: 2.7003x; 1.0372x over previous
#include <cuda_runtime.h>
#include <cuda_bf16.h>
#include <cstdint>

#define NU 100000
#define NS 50000
#define NG 50
#define NW 20000
#define NT 10
#define CC 64
#define FF 384
#define E_US 1000000
#define E_GS 150000
#define E_WS 50000
#define E_TS 50000
#define E_LI 200000

#define CNT_U   0
#define CNT_SU  (NU)
#define CNT_SG  (NU+NS)
#define CNT_SW  (NU+2*NS)
#define CNT_ST  (NU+3*NS)
#define CNT_G   (NU+4*NS)
#define CNT_W   (NU+4*NS+NG)
#define CNT_T   (NU+4*NS+NG+NW)
#define CNT_TOT (NU+4*NS+NG+NW+NT)

#define N_SCAN  (NU + 4*NS)                       // 300000
#define CSR_TOT (2*E_US + E_GS + E_WS + E_TS)     // 2250000
#define CHUNK   1024
#define NCHUNK  ((N_SCAN + CHUNK - 1) / CHUNK)    // 293

#define AGG_G 0
#define AGG_W ((size_t)NG*CC)
#define AGG_T ((size_t)(NG+NW)*CC)
#define AGG_TOT ((size_t)(NG+NW+NT)*CC)

// block-count constants for packed dispatch
#define U_BLK 782     // cdiv(NU,128)
#define S_BLK 391     // cdiv(NS,128)
#define W_BLK 157     // cdiv(NW,128)

// ---------------- scratch ----------------
__device__ int   g_cnt[CNT_TOT + N_SCAN];        // cnt + cur in one memset
__device__ int   g_off[N_SCAN + 1];
__device__ int   g_csum[NCHUNK];
__device__ int   g_csr[CSR_TOT];
__device__ float g_agg[AGG_TOT];

__device__ float g_xs[NS*CC];
__device__ float g_yu[NU*CC], g_ys[NS*CC];
__device__ float g_xu2[NU*CC], g_xs2[NS*CC];
__device__ float g_tU[NU*CC], g_tS[NS*CC], g_tG[NG*CC], g_tW[NW*CC], g_tT[NT*CC];
__device__ float g_tU2[NU*CC], g_tS2[NS*CC], g_tG2[NG*CC], g_tW2[NW*CC], g_tT2[NT*CC];
__device__ float g_xwp[NW*CC], g_xgp[NG*CC], g_xtp[NT*CC];
__device__ float g_WrS1[CC*CC], g_blS1[CC], g_WrS2[CC*CC], g_blS2[CC];

// ---------------- bf16 split helpers ----------------
__device__ __forceinline__ void split2(float x, float y, uint32_t& hi, uint32_t& lo) {
    __nv_bfloat162 h = __floats2bfloat162_rn(x, y);
    float2 hf = __bfloat1622float2(h);
    __nv_bfloat162 l = __floats2bfloat162_rn(x - hf.x, y - hf.y);
    hi = *(uint32_t*)&h;
    lo = *(uint32_t*)&l;
}
__device__ __forceinline__ void mma16(float* d, const uint32_t* a, uint32_t b0, uint32_t b1) {
    asm("mma.sync.aligned.m16n8k16.row.col.f32.bf16.bf16.f32 "
        "{%0,%1,%2,%3}, {%4,%5,%6,%7}, {%8,%9}, {%0,%1,%2,%3};"
        : "+f"(d[0]), "+f"(d[1]), "+f"(d[2]), "+f"(d[3])
        : "r"(a[0]), "r"(a[1]), "r"(a[2]), "r"(a[3]), "r"(b0), "r"(b1));
}

__device__ __forceinline__ void stage_w(const float* W, int ld, int k0,
                                        uint32_t (*Whi)[36], uint32_t (*Wlo)[36], int tid) {
#pragma unroll
    for (int i = tid; i < 64 * 32; i += 256) {
        int n = i >> 5, kp = i & 31;
        float2 w = *(const float2*)(W + (size_t)n * ld + k0 + 2 * kp);
        split2(w.x, w.y, Whi[n][kp], Wlo[n][kp]);
    }
}

__device__ __forceinline__ void mma_shared(float (*acc)[4], const uint32_t* ah, const uint32_t* al,
                                           const uint32_t (*Whi)[36], const uint32_t (*Wlo)[36],
                                           int ks, int g, int tg) {
#pragma unroll
    for (int j = 0; j < 8; j++) {
        uint32_t bh0 = Whi[j*8+g][ks*8+tg], bh1 = Whi[j*8+g][ks*8+tg+4];
        uint32_t bl0 = Wlo[j*8+g][ks*8+tg], bl1 = Wlo[j*8+g][ks*8+tg+4];
        mma16(acc[j], ah, bh0, bh1);
        mma16(acc[j], al, bh0, bh1);
        mma16(acc[j], ah, bl0, bl1);
    }
}

__device__ __forceinline__ void load_afrag(const float* A0, const float* A1, int kk, int relu,
                                           uint32_t* ah, uint32_t* al) {
    float2 a00 = *(const float2*)(A0 + kk);
    float2 a10 = *(const float2*)(A1 + kk);
    float2 a01 = *(const float2*)(A0 + kk + 8);
    float2 a11 = *(const float2*)(A1 + kk + 8);
    if (relu) {
        a00.x=fmaxf(a00.x,0.f); a00.y=fmaxf(a00.y,0.f);
        a10.x=fmaxf(a10.x,0.f); a10.y=fmaxf(a10.y,0.f);
        a01.x=fmaxf(a01.x,0.f); a01.y=fmaxf(a01.y,0.f);
        a11.x=fmaxf(a11.x,0.f); a11.y=fmaxf(a11.y,0.f);
    }
    split2(a00.x, a00.y, ah[0], al[0]);
    split2(a10.x, a10.y, ah[1], al[1]);
    split2(a01.x, a01.y, ah[2], al[2]);
    split2(a11.x, a11.y, ah[3], al[3]);
}

__device__ __forceinline__ void chain_dual(const float (*e)[4],
                                           const float* Wc0, const float* Wc1,
                                           float (*a2a)[4], float (*a2b)[4], int g, int tg) {
#pragma unroll
    for (int jj = 0; jj < 4; jj++) {
        uint32_t ah[4], al[4];
        split2(e[2*jj][0],   e[2*jj][1],   ah[0], al[0]);
        split2(e[2*jj][2],   e[2*jj][3],   ah[1], al[1]);
        split2(e[2*jj+1][0], e[2*jj+1][1], ah[2], al[2]);
        split2(e[2*jj+1][2], e[2*jj+1][3], ah[3], al[3]);
#pragma unroll
        for (int j = 0; j < 8; j++) {
            const float* wp0 = Wc0 + (size_t)(j*8+g)*CC + 16*jj + 2*tg;
            float2 w0 = *(const float2*)(wp0);
            float2 w1 = *(const float2*)(wp0 + 8);
            uint32_t bh0,bl0,bh1,bl1;
            split2(w0.x, w0.y, bh0, bl0);
            split2(w1.x, w1.y, bh1, bl1);
            mma16(a2a[j], ah, bh0, bh1);
            mma16(a2a[j], al, bh0, bh1);
            mma16(a2a[j], ah, bl0, bl1);
            if (Wc1) {
                const float* wp1 = Wc1 + (size_t)(j*8+g)*CC + 16*jj + 2*tg;
                float2 v0 = *(const float2*)(wp1);
                float2 v1 = *(const float2*)(wp1 + 8);
                split2(v0.x, v0.y, bh0, bl0);
                split2(v1.x, v1.y, bh1, bl1);
                mma16(a2b[j], ah, bh0, bh1);
                mma16(a2b[j], al, bh0, bh1);
                mma16(a2b[j], ah, bl0, bl1);
            }
        }
    }
}

__device__ __forceinline__ void store_frag(const float (*acc)[4], const float* bias,
                                           float* out, int mr0, int M, int tg) {
#pragma unroll
    for (int j = 0; j < 8; j++) {
        int n = j*8 + 2*tg;
        float b0 = bias ? bias[n] : 0.f, b1 = bias ? bias[n+1] : 0.f;
        if (mr0 < M)
            *(float2*)(out + (size_t)mr0*CC + n) = make_float2(acc[j][0]+b0, acc[j][1]+b1);
        if (mr0+8 < M)
            *(float2*)(out + (size_t)(mr0+8)*CC + n) = make_float2(acc[j][2]+b0, acc[j][3]+b1);
    }
}

// ---------------- prep ----------------
__global__ void prep(const float* __restrict__ Wr1, const float* __restrict__ bl1,
                     const float* __restrict__ Wr2, const float* __restrict__ bl2) {
    int i = blockIdx.x * 256 + threadIdx.x;
    if (i < CC*CC) {
        g_WrS1[i] = Wr1[i] + Wr1[2*CC*CC+i] + Wr1[4*CC*CC+i] + Wr1[6*CC*CC+i];
        g_WrS2[i] = Wr2[i] + Wr2[2*CC*CC+i] + Wr2[4*CC*CC+i] + Wr2[6*CC*CC+i];
    }
    if (i < CC) {
        g_blS1[i] = bl1[i] + bl1[2*CC+i] + bl1[4*CC+i] + bl1[6*CC+i];
        g_blS2[i] = bl2[i] + bl2[2*CC+i] + bl2[4*CC+i] + bl2[6*CC+i];
    }
}

// ---------------- phase0 mega ----------------
struct P0Job {
    const float* A; const float* W; const float* bias; float* xout;
    const float* Wc0; const float* bc0; float* oc0;
    const float* Wc1; float* oc1;
    int M;
};

__global__ void __launch_bounds__(256) p0_mega(
    const P0Job j0, const P0Job j1,
    const int* __restrict__ u2s, const int* __restrict__ g2s,
    const int* __restrict__ w2s, const int* __restrict__ t2s,
    int* __restrict__ cnt)
{
    if (blockIdx.y == 2) {
        const int stride = gridDim.x * 256;
        int base = blockIdx.x * 256 + threadIdx.x;
        for (int i = base; i < E_US; i += stride) {
            atomicAdd(cnt + CNT_U  + u2s[i], 1);
            atomicAdd(cnt + CNT_SU + u2s[E_US + i], 1);
        }
        for (int i = base; i < E_GS; i += stride) {
            atomicAdd(cnt + CNT_G  + g2s[i], 1);
            atomicAdd(cnt + CNT_SG + g2s[E_GS + i], 1);
        }
        for (int i = base; i < E_WS; i += stride) {
            atomicAdd(cnt + CNT_W  + w2s[i], 1);
            atomicAdd(cnt + CNT_SW + w2s[E_WS + i], 1);
        }
        for (int i = base; i < E_TS; i += stride) {
            atomicAdd(cnt + CNT_T  + t2s[i], 1);
            atomicAdd(cnt + CNT_ST + t2s[E_TS + i], 1);
        }
        return;
    }
    const P0Job jb = blockIdx.y ? j1 : j0;
    const int m0 = blockIdx.x * 128;
    if (m0 >= jb.M) return;

    __shared__ uint32_t Whi[64][36], Wlo[64][36];
    const int tid = threadIdx.x, wid = tid >> 5, lane = tid & 31;
    const int g = lane >> 2, tg = lane & 3;

    float acc1[8][4];
#pragma unroll
    for (int j = 0; j < 8; j++) { acc1[j][0]=acc1[j][1]=acc1[j][2]=acc1[j][3]=0.f; }

    const int mtop = jb.M - 1;
    const int mr0 = m0 + wid * 16 + g;
    const float* A0 = jb.A + (size_t)min(mr0,     mtop) * FF;
    const float* A1 = jb.A + (size_t)min(mr0 + 8, mtop) * FF;

    for (int k0 = 0; k0 < FF; k0 += 64) {
        if (k0) __syncthreads();
        stage_w(jb.W, FF, k0, Whi, Wlo, tid);
        __syncthreads();
#pragma unroll
        for (int ks = 0; ks < 4; ks++) {
            uint32_t ah[4], al[4];
            load_afrag(A0, A1, k0 + ks*16 + 2*tg, 0, ah, al);
            mma_shared(acc1, ah, al, Whi, Wlo, ks, g, tg);
        }
    }

#pragma unroll
    for (int j = 0; j < 8; j++) {
        int n = j*8 + 2*tg;
        float b0 = jb.bias[n], b1 = jb.bias[n+1];
        acc1[j][0] += b0; acc1[j][1] += b1;
        acc1[j][2] += b0; acc1[j][3] += b1;
    }
    if (jb.xout) store_frag(acc1, nullptr, jb.xout, mr0, jb.M, tg);

    float a2a[8][4], a2b[8][4];
#pragma unroll
    for (int j = 0; j < 8; j++) {
        a2a[j][0]=a2a[j][1]=a2a[j][2]=a2a[j][3]=0.f;
        a2b[j][0]=a2b[j][1]=a2b[j][2]=a2b[j][3]=0.f;
    }
    chain_dual(acc1, jb.Wc0, jb.Wc1, a2a, a2b, g, tg);
    store_frag(a2a, jb.bc0, jb.oc0, mr0, jb.M, tg);
    store_frag(a2b, nullptr, jb.oc1, mr0, jb.M, tg);
}

// ---------------- scan: chunk sums, then merged base+chunk scan ----------------
__global__ void scan1(const int* __restrict__ cnt, int* __restrict__ csum) {
    __shared__ int sh[8];
    int c = blockIdx.x, t = threadIdx.x, base = c * CHUNK;
    int s = 0;
#pragma unroll
    for (int q = 0; q < 4; q++) {
        int idx = base + t*4 + q;
        if (idx < N_SCAN) s += cnt[idx];
    }
    for (int o = 16; o; o >>= 1) s += __shfl_down_sync(~0u, s, o);
    if ((t & 31) == 0) sh[t >> 5] = s;
    __syncthreads();
    if (t == 0) { int tot = 0; for (int w = 0; w < 8; w++) tot += sh[w]; csum[c] = tot; }
}

__global__ void scan23(const int* __restrict__ cnt, const int* __restrict__ csum,
                       int* __restrict__ off) {
    __shared__ int sh[8], sh2[8], basev;
    int c = blockIdx.x, t = threadIdx.x;
    int lane = t & 31, w = t >> 5;

    // chunk base = sum of csum[0..c-1]
    int p = 0;
    for (int i = t; i < c; i += 256) p += csum[i];
    for (int o = 16; o; o >>= 1) p += __shfl_down_sync(~0u, p, o);
    if (lane == 0) sh2[w] = p;
    __syncthreads();
    if (t == 0) { int a = 0; for (int i = 0; i < 8; i++) a += sh2[i]; basev = a; }
    __syncthreads();
    const int cbase = basev;

    int base = c * CHUNK;
    int v[4]; int s = 0;
#pragma unroll
    for (int q = 0; q < 4; q++) {
        int idx = base + t*4 + q;
        v[q] = (idx < N_SCAN) ? cnt[idx] : 0;
        s += v[q];
    }
    int incl = s;
    for (int o = 1; o < 32; o <<= 1) {
        int x = __shfl_up_sync(~0u, incl, o);
        if (lane >= o) incl += x;
    }
    if (lane == 31) sh[w] = incl;
    __syncthreads();
    if (t == 0) { int a = 0; for (int i = 0; i < 8; i++) { int x = sh[i]; sh[i] = a; a += x; } }
    __syncthreads();
    int excl = incl - s + sh[w] + cbase;
#pragma unroll
    for (int q = 0; q < 4; q++) {
        int idx = base + t*4 + q;
        if (idx < N_SCAN) off[idx] = excl;
        excl += v[q];
        if (idx == N_SCAN - 1) off[N_SCAN] = excl;
    }
}

// ---------------- CSR fill ----------------
__global__ void fill_csr(const int* __restrict__ u2s, const int* __restrict__ g2s,
                         const int* __restrict__ w2s, const int* __restrict__ t2s,
                         const int* __restrict__ off, int* __restrict__ cur,
                         int* __restrict__ csr) {
    int i = blockIdx.x * 256 + threadIdx.x;
    if (i < E_US) {
        int u = u2s[i], s = u2s[E_US + i];
        int n0 = CNT_SU + s;
        csr[off[n0] + atomicAdd(cur + n0, 1)] = u;
        int n1 = CNT_U + u;
        csr[off[n1] + atomicAdd(cur + n1, 1)] = s;
    }
    if (i < E_GS) {
        int gg = g2s[i], s = g2s[E_GS + i];
        int n = CNT_SG + s;
        csr[off[n] + atomicAdd(cur + n, 1)] = gg;
    }
    if (i < E_WS) {
        int ww = w2s[i], s = w2s[E_WS + i];
        int n = CNT_SW + s;
        csr[off[n] + atomicAdd(cur + n, 1)] = ww;
    }
    if (i < E_TS) {
        int tt = t2s[i], s = t2s[E_TS + i];
        int n = CNT_ST + s;
        csr[off[n] + atomicAdd(cur + n, 1)] = tt;
    }
}

// ---------------- GEMM bodies (parameterized by block offset) ----------------
struct DualJob {
    const float* A; const float* W0; const float* b0; float* o0;
    const float* W1; const float* b1; float* o1; int M; int relu_in;
};
struct FBJob {
    const float* A; const float* W1; const float* accin; const int* cnt;
    const float* Wc; float* out; int M;
};

__device__ __forceinline__ void dual_body(const DualJob& jb, int bx,
                                          uint32_t (*WhiA)[36], uint32_t (*WloA)[36],
                                          uint32_t (*WhiB)[36], uint32_t (*WloB)[36]) {
    const int m0 = bx * 128;
    const int tid = threadIdx.x, wid = tid >> 5, lane = tid & 31;
    const int g = lane >> 2, tg = lane & 3;

    stage_w(jb.W0, CC, 0, WhiA, WloA, tid);
    stage_w(jb.W1, CC, 0, WhiB, WloB, tid);
    __syncthreads();

    float acc[2][8][4];
#pragma unroll
    for (int w = 0; w < 2; w++)
#pragma unroll
        for (int j = 0; j < 8; j++) { acc[w][j][0]=acc[w][j][1]=acc[w][j][2]=acc[w][j][3]=0.f; }

    const int mtop = jb.M - 1;
    const int mr0 = m0 + wid * 16 + g;
    const float* A0 = jb.A + (size_t)min(mr0,     mtop) * CC;
    const float* A1 = jb.A + (size_t)min(mr0 + 8, mtop) * CC;

#pragma unroll
    for (int ks = 0; ks < 4; ks++) {
        uint32_t ah[4], al[4];
        load_afrag(A0, A1, ks*16 + 2*tg, jb.relu_in, ah, al);
        mma_shared(acc[0], ah, al, WhiA, WloA, ks, g, tg);
        mma_shared(acc[1], ah, al, WhiB, WloB, ks, g, tg);
    }
    store_frag(acc[0], jb.b0, jb.o0, mr0, jb.M, tg);
    store_frag(acc[1], jb.b1, jb.o1, mr0, jb.M, tg);
}

__device__ __forceinline__ void fb_body(const FBJob& jb, int bx,
                                        uint32_t (*Whi)[36], uint32_t (*Wlo)[36]) {
    const int m0 = bx * 128;
    const int tid = threadIdx.x, wid = tid >> 5, lane = tid & 31;
    const int g = lane >> 2, tg = lane & 3;

    stage_w(jb.W1, CC, 0, Whi, Wlo, tid);
    __syncthreads();

    float acc1[8][4];
#pragma unroll
    for (int j = 0; j < 8; j++) { acc1[j][0]=acc1[j][1]=acc1[j][2]=acc1[j][3]=0.f; }

    const int mtop = jb.M - 1;
    const int mr0 = m0 + wid * 16 + g;
    const int r0 = min(mr0, mtop), r1 = min(mr0 + 8, mtop);
    const float* A0 = jb.A + (size_t)r0 * CC;
    const float* A1 = jb.A + (size_t)r1 * CC;

#pragma unroll
    for (int ks = 0; ks < 4; ks++) {
        uint32_t ah[4], al[4];
        load_afrag(A0, A1, ks*16 + 2*tg, 0, ah, al);
        mma_shared(acc1, ah, al, Whi, Wlo, ks, g, tg);
    }

    const float s0 = 1.f / fmaxf((float)jb.cnt[r0], 1.f);
    const float s1 = 1.f / fmaxf((float)jb.cnt[r1], 1.f);
#pragma unroll
    for (int j = 0; j < 8; j++) {
        int n = j*8 + 2*tg;
        float2 c0 = *(const float2*)(jb.accin + (size_t)r0 * CC + n);
        float2 c1 = *(const float2*)(jb.accin + (size_t)r1 * CC + n);
        acc1[j][0] = fmaxf(acc1[j][0]*s0 + c0.x, 0.f);
        acc1[j][1] = fmaxf(acc1[j][1]*s0 + c0.y, 0.f);
        acc1[j][2] = fmaxf(acc1[j][2]*s1 + c1.x, 0.f);
        acc1[j][3] = fmaxf(acc1[j][3]*s1 + c1.y, 0.f);
    }

    float a2[8][4], dummy[1][4];
#pragma unroll
    for (int j = 0; j < 8; j++) { a2[j][0]=a2[j][1]=a2[j][2]=a2[j][3]=0.f; }
    chain_dual(acc1, jb.Wc, nullptr, a2, dummy, g, tg);
    store_frag(a2, nullptr, jb.out, mr0, jb.M, tg);
}

// ---------------- waveA: 3 small duals + s->g/w/t scatter, packed 1-D ----------------
struct ScatJob { const float* x; const int* src; const int* dst; float* out; };

#define SCAT_E  (E_GS + E_WS + E_TS)
#define SCAT_BLK ((SCAT_E * 8 + 255) / 256)
#define WA_BASE1 (W_BLK)          // g job
#define WA_BASE2 (W_BLK + 1)      // t job
#define WA_SCAT  (W_BLK + 2)      // scatter range start

__global__ void __launch_bounds__(256) waveA(
    const DualJob jw, const DualJob jg, const DualJob jt,
    const ScatJob s0, const ScatJob s1, const ScatJob s2)
{
    __shared__ uint32_t Whi[2][64][36], Wlo[2][64][36];
    int bx = blockIdx.x;
    if (bx < W_BLK)       { dual_body(jw, bx,            Whi[0], Wlo[0], Whi[1], Wlo[1]); return; }
    if (bx == WA_BASE1)   { dual_body(jg, 0,             Whi[0], Wlo[0], Whi[1], Wlo[1]); return; }
    if (bx == WA_BASE2)   { dual_body(jt, 0,             Whi[0], Wlo[0], Whi[1], Wlo[1]); return; }
    // scatter
    int gid = (bx - WA_SCAT) * 256 + threadIdx.x;
    int ge = gid >> 3;
    if (ge >= SCAT_E) return;
    int part = gid & 7;
    const ScatJob jb = (ge < E_GS) ? s0 : (ge < E_GS + E_WS ? s1 : s2);
    int e = (ge < E_GS) ? ge : (ge < E_GS + E_WS ? ge - E_GS : ge - E_GS - E_WS);
    int s = jb.src[e], d = jb.dst[e];
    const float4* xp = (const float4*)(jb.x + (size_t)s * CC);
    float4*       op = (float4*)(jb.out + (size_t)d * CC);
    atomicAdd(op + part,     xp[part]);
    atomicAdd(op + part + 8, xp[part + 8]);
}

// ---------------- wave2: 2 big duals + 3 fusedB chains, packed 1-D ----------------
#define W2_B0 0                    // yu dual: U_BLK
#define W2_B1 (U_BLK)              // ys dual: S_BLK
#define W2_B2 (U_BLK + S_BLK)      // fb w: W_BLK
#define W2_B3 (U_BLK + S_BLK + W_BLK)      // fb g: 1
#define W2_B4 (U_BLK + S_BLK + W_BLK + 1)  // fb t: 1
#define W2_TOT (U_BLK + S_BLK + W_BLK + 2)

__global__ void __launch_bounds__(256) wave2(
    const DualJob d0, const DualJob d1,
    const FBJob f0, const FBJob f1, const FBJob f2)
{
    __shared__ uint32_t Whi[2][64][36], Wlo[2][64][36];
    int bx = blockIdx.x;
    if (bx < W2_B1)      { dual_body(d0, bx,          Whi[0], Wlo[0], Whi[1], Wlo[1]); return; }
    if (bx < W2_B2)      { dual_body(d1, bx - W2_B1,  Whi[0], Wlo[0], Whi[1], Wlo[1]); return; }
    if (bx < W2_B3)      { fb_body(f0, bx - W2_B2,    Whi[0], Wlo[0]); return; }
    if (bx == W2_B3)     { fb_body(f1, 0,             Whi[0], Wlo[0]); return; }
    fb_body(f2, 0, Whi[0], Wlo[0]);
}

// ---------------- warp-per-node gather: 2 edges/iter, float4 lanes ----------------
__global__ void __launch_bounds__(256) gather_nodes(
    const float* __restrict__ tU, const float* __restrict__ tS,
    const float* __restrict__ tG, const float* __restrict__ tW, const float* __restrict__ tT,
    float* __restrict__ outS, float* __restrict__ outU,
    const int* __restrict__ off, const int* __restrict__ csr)
{
    int gw = (blockIdx.x * 256 + threadIdx.x) >> 5;
    int lane = threadIdx.x & 31;
    int half = lane >> 4;          // which edge of the pair
    int col = (lane & 15) * 4;     // float4 column
    float4 s = make_float4(0.f, 0.f, 0.f, 0.f);
    float* o;

    if (gw < NS) {
        const int d = gw;
        const int node[4] = { CNT_SU + d, CNT_SG + d, CNT_SW + d, CNT_ST + d };
        const float* buf[4] = { tU, tG, tW, tT };
#pragma unroll
        for (int f = 0; f < 4; f++) {
            int b = off[node[f]], e = off[node[f] + 1];
            float4 fa = make_float4(0.f, 0.f, 0.f, 0.f);
#pragma unroll 2
            for (int i = b + half; i < e; i += 2) {
                int src = csr[i];
                float4 v = *(const float4*)(buf[f] + (size_t)src * CC + col);
                fa.x += v.x; fa.y += v.y; fa.z += v.z; fa.w += v.w;
            }
            float inv = 1.f / fmaxf((float)(e - b), 1.f);
            s.x += fa.x * inv; s.y += fa.y * inv; s.z += fa.z * inv; s.w += fa.w * inv;
        }
        o = outS + (size_t)d * CC + col;
    } else if (gw < NS + NU) {
        const int d = gw - NS;
        int b = off[CNT_U + d], e = off[CNT_U + d + 1];
        float4 fa = make_float4(0.f, 0.f, 0.f, 0.f);
#pragma unroll 2
        for (int i = b + half; i < e; i += 2) {
            int src = csr[i];
            float4 v = *(const float4*)(tS + (size_t)src * CC + col);
            fa.x += v.x; fa.y += v.y; fa.z += v.z; fa.w += v.w;
        }
        float inv = 1.f / fmaxf((float)(e - b), 1.f);
        s.x = fa.x * inv; s.y = fa.y * inv; s.z = fa.z * inv; s.w = fa.w * inv;
        o = outU + (size_t)d * CC + col;
    } else return;

    // combine the two half-warps
    s.x += __shfl_xor_sync(~0u, s.x, 16);
    s.y += __shfl_xor_sync(~0u, s.y, 16);
    s.z += __shfl_xor_sync(~0u, s.z, 16);
    s.w += __shfl_xor_sync(~0u, s.w, 16);
    if (half == 0) {
        float4 c = *(const float4*)o;
        *(float4*)o = make_float4(c.x + s.x, c.y + s.y, c.z + s.z, c.w + s.w);
    }
}

// ---------------- classifier ----------------
__global__ void dot_score(const float* __restrict__ xu, const float* __restrict__ xs,
                          const int* __restrict__ ui, const int* __restrict__ si,
                          float* __restrict__ out, int E) {
    int gid = blockIdx.x * blockDim.x + threadIdx.x;
    int e = gid >> 4;
    int j = (gid & 15) << 2;
    int ec = (e < E) ? e : (E - 1);
    float4 a = *(const float4*)(xu + (size_t)ui[ec] * CC + j);
    float4 b = *(const float4*)(xs + (size_t)si[ec] * CC + j);
    float d = a.x*b.x + a.y*b.y + a.z*b.z + a.w*b.w;
    d += __shfl_xor_sync(0xffffffffu, d, 1);
    d += __shfl_xor_sync(0xffffffffu, d, 2);
    d += __shfl_xor_sync(0xffffffffu, d, 4);
    d += __shfl_xor_sync(0xffffffffu, d, 8);
    if ((gid & 15) == 0 && e < E) out[e] = d;
}

static inline int cdiv(int a, int b) { return (a + b - 1) / b; }

extern "C" void kernel_launch(void* const* d_in, const int* in_sizes, int n_in,
                              void* d_out, int out_size)
{
    const float* reviews  = (const float*)d_in[0];
    const float* overview = (const float*)d_in[1];
    const float* g_emb    = (const float*)d_in[2];
    const float* w_emb    = (const float*)d_in[3];
    const float* t_emb    = (const float*)d_in[4];
    const float* Wu  = (const float*)d_in[5];
    const float* bu  = (const float*)d_in[6];
    const float* Wsw = (const float*)d_in[7];
    const float* bs  = (const float*)d_in[8];
    const float* Wl1 = (const float*)d_in[9];
    const float* bl1 = (const float*)d_in[10];
    const float* Wr1 = (const float*)d_in[11];
    const float* Wl2 = (const float*)d_in[12];
    const float* bl2 = (const float*)d_in[13];
    const float* Wr2 = (const float*)d_in[14];
    const int* e_u2s = (const int*)d_in[15];
    const int* e_g2s = (const int*)d_in[16];
    const int* e_w2s = (const int*)d_in[17];
    const int* e_t2s = (const int*)d_in[18];
    const int* eli   = (const int*)d_in[19];
    float* out = (float*)d_out;

    int *cnt,*off,*csum,*csr;
    float *agg,*xs,*yu,*ys,*xu2,*xs2;
    float *tU,*tS,*tG,*tW,*tT,*tU2,*tS2,*tG2,*tW2,*tT2,*xwp,*xgp,*xtp;
    float *WrS1,*blS1,*WrS2,*blS2;
    cudaGetSymbolAddress((void**)&cnt,  g_cnt);
    cudaGetSymbolAddress((void**)&off,  g_off);
    cudaGetSymbolAddress((void**)&csum, g_csum);
    cudaGetSymbolAddress((void**)&csr,  g_csr);
    cudaGetSymbolAddress((void**)&agg,  g_agg);
    cudaGetSymbolAddress((void**)&xs,   g_xs);
    cudaGetSymbolAddress((void**)&yu,   g_yu);
    cudaGetSymbolAddress((void**)&ys,   g_ys);
    cudaGetSymbolAddress((void**)&xu2,  g_xu2);
    cudaGetSymbolAddress((void**)&xs2,  g_xs2);
    cudaGetSymbolAddress((void**)&tU,   g_tU);
    cudaGetSymbolAddress((void**)&tS,   g_tS);
    cudaGetSymbolAddress((void**)&tG,   g_tG);
    cudaGetSymbolAddress((void**)&tW,   g_tW);
    cudaGetSymbolAddress((void**)&tT,   g_tT);
    cudaGetSymbolAddress((void**)&tU2,  g_tU2);
    cudaGetSymbolAddress((void**)&tS2,  g_tS2);
    cudaGetSymbolAddress((void**)&tG2,  g_tG2);
    cudaGetSymbolAddress((void**)&tW2,  g_tW2);
    cudaGetSymbolAddress((void**)&tT2,  g_tT2);
    cudaGetSymbolAddress((void**)&xwp,  g_xwp);
    cudaGetSymbolAddress((void**)&xgp,  g_xgp);
    cudaGetSymbolAddress((void**)&xtp,  g_xtp);
    cudaGetSymbolAddress((void**)&WrS1, g_WrS1);
    cudaGetSymbolAddress((void**)&blS1, g_blS1);
    cudaGetSymbolAddress((void**)&WrS2, g_WrS2);
    cudaGetSymbolAddress((void**)&blS2, g_blS2);

    int* cur = cnt + CNT_TOT;
    const int W44 = CC*CC;

    // ---- init ----
    cudaMemsetAsync(cnt, 0, (CNT_TOT + N_SCAN) * sizeof(int));
    cudaMemsetAsync(agg, 0, AGG_TOT * sizeof(float));
    prep<<<16, 256>>>(Wr1, bl1, Wr2, bl2);

    // ---- phase0: transforms + chained layer-1 pre-terms + deg count ----
    {
        P0Job ju = { reviews,  Wu,  bu, nullptr,
                     Wr1 + 1*W44, bl1 + 1*CC, yu,
                     Wl1 + 0*W44, tU, NU };
        P0Job js = { overview, Wsw, bs, xs,
                     WrS1, blS1, ys,
                     Wl1 + 1*W44, tS, NS };
        p0_mega<<<dim3(U_BLK, 3), 256>>>(ju, js, e_u2s, e_g2s, e_w2s, e_t2s, cnt);
    }

    // ---- CSR build ----
    scan1<<<NCHUNK, 256>>>(cnt, csum);
    scan23<<<NCHUNK, 256>>>(cnt, csum, off);
    fill_csr<<<cdiv(E_US,256), 256>>>(e_u2s, e_g2s, e_w2s, e_t2s, off, cur, csr);

    // ---- waveA: small embedding duals + s->g/w/t scatter (packed) ----
    {
        DualJob jw = { w_emb, Wl1 + 4*W44, nullptr, tW, Wr1 + 5*W44, bl1 + 5*CC, xwp, NW, 0 };
        DualJob jg = { g_emb, Wl1 + 2*W44, nullptr, tG, Wr1 + 3*W44, bl1 + 3*CC, xgp, NG, 0 };
        DualJob jt = { t_emb, Wl1 + 6*W44, nullptr, tT, Wr1 + 7*W44, bl1 + 7*CC, xtp, NT, 0 };
        ScatJob s0 = { xs, e_g2s + E_GS, e_g2s, agg + AGG_G };
        ScatJob s1 = { xs, e_w2s + E_WS, e_w2s, agg + AGG_W };
        ScatJob s2 = { xs, e_t2s + E_TS, e_t2s, agg + AGG_T };
        waveA<<<WA_SCAT + SCAT_BLK, 256>>>(jw, jg, jt, s0, s1, s2);
    }

    // ---- gather 1 ----
    gather_nodes<<<cdiv((NS+NU)*32, 256), 256>>>(tU, tS, tG, tW, tT, ys, yu, off, csr);

    // ---- wave2: layer-2 duals + fused layer1-finalize chains (packed) ----
    {
        DualJob d0 = { yu, Wl2 + 0*W44, nullptr, tU2, Wr2 + 1*W44, bl2 + 1*CC, xu2, NU, 1 };
        DualJob d1 = { ys, WrS2,        blS2,    xs2, Wl2 + 1*W44, nullptr,    tS2, NS, 1 };
        FBJob f0 = { agg + AGG_W, Wl1 + 5*W44, xwp, cnt + CNT_W, Wl2 + 4*W44, tW2, NW };
        FBJob f1 = { agg + AGG_G, Wl1 + 3*W44, xgp, cnt + CNT_G, Wl2 + 2*W44, tG2, NG };
        FBJob f2 = { agg + AGG_T, Wl1 + 7*W44, xtp, cnt + CNT_T, Wl2 + 6*W44, tT2, NT };
        wave2<<<W2_TOT, 256>>>(d0, d1, f0, f1, f2);
    }

    // ---- gather 2 ----
    gather_nodes<<<cdiv((NS+NU)*32, 256), 256>>>(tU2, tS2, tG2, tW2, tT2, xs2, xu2, off, csr);

    // ---- classifier ----
    dot_score<<<E_LI*16/256, 256>>>(xu2, xs2, eli, eli + E_LI, out, E_LI);
}

// round 7
// speedup vs baseline: 2.7408x; 1.0150x over previous
#include <cuda_runtime.h>
#include <cuda_bf16.h>
#include <cuda_fp16.h>
#include <cstdint>

#define NU 100000
#define NS 50000
#define NG 50
#define NW 20000
#define NT 10
#define CC 64
#define FF 384
#define E_US 1000000
#define E_GS 150000
#define E_WS 50000
#define E_TS 50000
#define E_LI 200000

#define CNT_U   0
#define CNT_SU  (NU)
#define CNT_SG  (NU+NS)
#define CNT_SW  (NU+2*NS)
#define CNT_ST  (NU+3*NS)
#define CNT_G   (NU+4*NS)
#define CNT_W   (NU+4*NS+NG)
#define CNT_T   (NU+4*NS+NG+NW)
#define CNT_TOT (NU+4*NS+NG+NW+NT)

#define N_SCAN  (NU + 4*NS)
#define CSR_TOT (2*E_US + E_GS + E_WS + E_TS)
#define CHUNK   1024
#define NCHUNK  ((N_SCAN + CHUNK - 1) / CHUNK)

#define AGG_G 0
#define AGG_W ((size_t)NG*CC)
#define AGG_T ((size_t)(NG+NW)*CC)
#define AGG_TOT ((size_t)(NG+NW+NT)*CC)

#define U_BLK 782
#define S_BLK 391
#define W_BLK 157

// ---------------- scratch ----------------
__device__ int   g_cnt[CNT_TOT + N_SCAN];
__device__ int   g_off[N_SCAN + 1];
__device__ int   g_csum[NCHUNK];
__device__ int   g_csr[CSR_TOT];
__device__ float g_agg[AGG_TOT];

__device__ float g_xs[NS*CC];
__device__ float g_yu[NU*CC], g_ys[NS*CC];
__device__ float g_xu2[NU*CC], g_xs2[NS*CC];
__device__ __half g_tU[NU*CC], g_tS[NS*CC], g_tG[NG*CC], g_tW[NW*CC], g_tT[NT*CC];
__device__ __half g_tU2[NU*CC], g_tS2[NS*CC], g_tG2[NG*CC], g_tW2[NW*CC], g_tT2[NT*CC];
__device__ float g_xwp[NW*CC], g_xgp[NG*CC], g_xtp[NT*CC];
__device__ float g_WrS1[CC*CC], g_blS1[CC], g_WrS2[CC*CC], g_blS2[CC];

// ---------------- bf16 split helpers ----------------
__device__ __forceinline__ void split2(float x, float y, uint32_t& hi, uint32_t& lo) {
    __nv_bfloat162 h = __floats2bfloat162_rn(x, y);
    float2 hf = __bfloat1622float2(h);
    __nv_bfloat162 l = __floats2bfloat162_rn(x - hf.x, y - hf.y);
    hi = *(uint32_t*)&h;
    lo = *(uint32_t*)&l;
}
__device__ __forceinline__ void mma16(float* d, const uint32_t* a, uint32_t b0, uint32_t b1) {
    asm("mma.sync.aligned.m16n8k16.row.col.f32.bf16.bf16.f32 "
        "{%0,%1,%2,%3}, {%4,%5,%6,%7}, {%8,%9}, {%0,%1,%2,%3};"
        : "+f"(d[0]), "+f"(d[1]), "+f"(d[2]), "+f"(d[3])
        : "r"(a[0]), "r"(a[1]), "r"(a[2]), "r"(a[3]), "r"(b0), "r"(b1));
}

__device__ __forceinline__ void stage_w(const float* W, int ld, int k0,
                                        uint32_t (*Whi)[36], uint32_t (*Wlo)[36], int tid) {
#pragma unroll
    for (int i = tid; i < 64 * 32; i += 256) {
        int n = i >> 5, kp = i & 31;
        float2 w = *(const float2*)(W + (size_t)n * ld + k0 + 2 * kp);
        split2(w.x, w.y, Whi[n][kp], Wlo[n][kp]);
    }
}

__device__ __forceinline__ void mma_shared(float (*acc)[4], const uint32_t* ah, const uint32_t* al,
                                           const uint32_t (*Whi)[36], const uint32_t (*Wlo)[36],
                                           int ks, int g, int tg) {
#pragma unroll
    for (int j = 0; j < 8; j++) {
        uint32_t bh0 = Whi[j*8+g][ks*8+tg], bh1 = Whi[j*8+g][ks*8+tg+4];
        uint32_t bl0 = Wlo[j*8+g][ks*8+tg], bl1 = Wlo[j*8+g][ks*8+tg+4];
        mma16(acc[j], ah, bh0, bh1);
        mma16(acc[j], al, bh0, bh1);
        mma16(acc[j], ah, bl0, bl1);
    }
}

__device__ __forceinline__ void load_afrag(const float* A0, const float* A1, int kk, int relu,
                                           uint32_t* ah, uint32_t* al) {
    float2 a00 = *(const float2*)(A0 + kk);
    float2 a10 = *(const float2*)(A1 + kk);
    float2 a01 = *(const float2*)(A0 + kk + 8);
    float2 a11 = *(const float2*)(A1 + kk + 8);
    if (relu) {
        a00.x=fmaxf(a00.x,0.f); a00.y=fmaxf(a00.y,0.f);
        a10.x=fmaxf(a10.x,0.f); a10.y=fmaxf(a10.y,0.f);
        a01.x=fmaxf(a01.x,0.f); a01.y=fmaxf(a01.y,0.f);
        a11.x=fmaxf(a11.x,0.f); a11.y=fmaxf(a11.y,0.f);
    }
    split2(a00.x, a00.y, ah[0], al[0]);
    split2(a10.x, a10.y, ah[1], al[1]);
    split2(a01.x, a01.y, ah[2], al[2]);
    split2(a11.x, a11.y, ah[3], al[3]);
}

__device__ __forceinline__ void chain_dual(const float (*e)[4],
                                           const float* Wc0, const float* Wc1,
                                           float (*a2a)[4], float (*a2b)[4], int g, int tg) {
#pragma unroll
    for (int jj = 0; jj < 4; jj++) {
        uint32_t ah[4], al[4];
        split2(e[2*jj][0],   e[2*jj][1],   ah[0], al[0]);
        split2(e[2*jj][2],   e[2*jj][3],   ah[1], al[1]);
        split2(e[2*jj+1][0], e[2*jj+1][1], ah[2], al[2]);
        split2(e[2*jj+1][2], e[2*jj+1][3], ah[3], al[3]);
#pragma unroll
        for (int j = 0; j < 8; j++) {
            const float* wp0 = Wc0 + (size_t)(j*8+g)*CC + 16*jj + 2*tg;
            float2 w0 = *(const float2*)(wp0);
            float2 w1 = *(const float2*)(wp0 + 8);
            uint32_t bh0,bl0,bh1,bl1;
            split2(w0.x, w0.y, bh0, bl0);
            split2(w1.x, w1.y, bh1, bl1);
            mma16(a2a[j], ah, bh0, bh1);
            mma16(a2a[j], al, bh0, bh1);
            mma16(a2a[j], ah, bl0, bl1);
            if (Wc1) {
                const float* wp1 = Wc1 + (size_t)(j*8+g)*CC + 16*jj + 2*tg;
                float2 v0 = *(const float2*)(wp1);
                float2 v1 = *(const float2*)(wp1 + 8);
                split2(v0.x, v0.y, bh0, bl0);
                split2(v1.x, v1.y, bh1, bl1);
                mma16(a2b[j], ah, bh0, bh1);
                mma16(a2b[j], al, bh0, bh1);
                mma16(a2b[j], ah, bl0, bl1);
            }
        }
    }
}

__device__ __forceinline__ void store_frag(const float (*acc)[4], const float* bias,
                                           float* out, int mr0, int M, int tg) {
#pragma unroll
    for (int j = 0; j < 8; j++) {
        int n = j*8 + 2*tg;
        float b0 = bias ? bias[n] : 0.f, b1 = bias ? bias[n+1] : 0.f;
        if (mr0 < M)
            *(float2*)(out + (size_t)mr0*CC + n) = make_float2(acc[j][0]+b0, acc[j][1]+b1);
        if (mr0+8 < M)
            *(float2*)(out + (size_t)(mr0+8)*CC + n) = make_float2(acc[j][2]+b0, acc[j][3]+b1);
    }
}

__device__ __forceinline__ void store_frag_h(const float (*acc)[4], __half* out,
                                             int mr0, int M, int tg) {
#pragma unroll
    for (int j = 0; j < 8; j++) {
        int n = j*8 + 2*tg;
        if (mr0 < M)
            *(__half2*)(out + (size_t)mr0*CC + n) = __floats2half2_rn(acc[j][0], acc[j][1]);
        if (mr0+8 < M)
            *(__half2*)(out + (size_t)(mr0+8)*CC + n) = __floats2half2_rn(acc[j][2], acc[j][3]);
    }
}

// ---------------- job structs ----------------
struct DualJob {              // o0 (half, no bias) = A@W0^T ; o1 (float) = A@W1^T + b1
    const float* A; const float* W0; __half* o0;
    const float* W1; const float* b1; float* o1; int M; int relu_in;
};
struct FBJob {
    const float* A; const float* W1; const float* accin; const int* cnt;
    const float* Wc; __half* out; int M;
};
struct P0Job {
    const float* A; const float* W; const float* bias; float* xout;
    const float* Wc0; const float* bc0; float* oc0;
    const float* Wc1; __half* oc1;
    int M;
};
struct ScatJob { const float* x; const int* src; const int* dst; float* out; };

// ---------------- GEMM bodies ----------------
__device__ __forceinline__ void dual_body(const DualJob& jb, int bx,
                                          uint32_t (*WhiA)[36], uint32_t (*WloA)[36],
                                          uint32_t (*WhiB)[36], uint32_t (*WloB)[36]) {
    const int m0 = bx * 128;
    const int tid = threadIdx.x, wid = tid >> 5, lane = tid & 31;
    const int g = lane >> 2, tg = lane & 3;

    stage_w(jb.W0, CC, 0, WhiA, WloA, tid);
    stage_w(jb.W1, CC, 0, WhiB, WloB, tid);
    __syncthreads();

    float acc[2][8][4];
#pragma unroll
    for (int w = 0; w < 2; w++)
#pragma unroll
        for (int j = 0; j < 8; j++) { acc[w][j][0]=acc[w][j][1]=acc[w][j][2]=acc[w][j][3]=0.f; }

    const int mtop = jb.M - 1;
    const int mr0 = m0 + wid * 16 + g;
    const float* A0 = jb.A + (size_t)min(mr0,     mtop) * CC;
    const float* A1 = jb.A + (size_t)min(mr0 + 8, mtop) * CC;

#pragma unroll
    for (int ks = 0; ks < 4; ks++) {
        uint32_t ah[4], al[4];
        load_afrag(A0, A1, ks*16 + 2*tg, jb.relu_in, ah, al);
        mma_shared(acc[0], ah, al, WhiA, WloA, ks, g, tg);
        mma_shared(acc[1], ah, al, WhiB, WloB, ks, g, tg);
    }
    store_frag_h(acc[0], jb.o0, mr0, jb.M, tg);
    store_frag(acc[1], jb.b1, jb.o1, mr0, jb.M, tg);
}

__device__ __forceinline__ void fb_body(const FBJob& jb, int bx,
                                        uint32_t (*Whi)[36], uint32_t (*Wlo)[36]) {
    const int m0 = bx * 128;
    const int tid = threadIdx.x, wid = tid >> 5, lane = tid & 31;
    const int g = lane >> 2, tg = lane & 3;

    stage_w(jb.W1, CC, 0, Whi, Wlo, tid);
    __syncthreads();

    float acc1[8][4];
#pragma unroll
    for (int j = 0; j < 8; j++) { acc1[j][0]=acc1[j][1]=acc1[j][2]=acc1[j][3]=0.f; }

    const int mtop = jb.M - 1;
    const int mr0 = m0 + wid * 16 + g;
    const int r0 = min(mr0, mtop), r1 = min(mr0 + 8, mtop);
    const float* A0 = jb.A + (size_t)r0 * CC;
    const float* A1 = jb.A + (size_t)r1 * CC;

#pragma unroll
    for (int ks = 0; ks < 4; ks++) {
        uint32_t ah[4], al[4];
        load_afrag(A0, A1, ks*16 + 2*tg, 0, ah, al);
        mma_shared(acc1, ah, al, Whi, Wlo, ks, g, tg);
    }

    const float s0 = 1.f / fmaxf((float)jb.cnt[r0], 1.f);
    const float s1 = 1.f / fmaxf((float)jb.cnt[r1], 1.f);
#pragma unroll
    for (int j = 0; j < 8; j++) {
        int n = j*8 + 2*tg;
        float2 c0 = *(const float2*)(jb.accin + (size_t)r0 * CC + n);
        float2 c1 = *(const float2*)(jb.accin + (size_t)r1 * CC + n);
        acc1[j][0] = fmaxf(acc1[j][0]*s0 + c0.x, 0.f);
        acc1[j][1] = fmaxf(acc1[j][1]*s0 + c0.y, 0.f);
        acc1[j][2] = fmaxf(acc1[j][2]*s1 + c1.x, 0.f);
        acc1[j][3] = fmaxf(acc1[j][3]*s1 + c1.y, 0.f);
    }

    float a2[8][4], dummy[1][4];
#pragma unroll
    for (int j = 0; j < 8; j++) { a2[j][0]=a2[j][1]=a2[j][2]=a2[j][3]=0.f; }
    chain_dual(acc1, jb.Wc, nullptr, a2, dummy, g, tg);
    store_frag_h(a2, jb.out, mr0, jb.M, tg);
}

// ---------------- launch 1: small duals + prep + deg count (needs inputs only) ----
#define PD_PREP (W_BLK + 2)
#define PD_DEG  (W_BLK + 2 + 16)
#define PD_DEGBLK 512
#define PD_TOT  (PD_DEG + PD_DEGBLK)

__global__ void __launch_bounds__(256) prep_deg_duals(
    const DualJob jw, const DualJob jg, const DualJob jt,
    const float* __restrict__ Wr1, const float* __restrict__ bl1,
    const float* __restrict__ Wr2, const float* __restrict__ bl2,
    const int* __restrict__ u2s, const int* __restrict__ g2s,
    const int* __restrict__ w2s, const int* __restrict__ t2s,
    int* __restrict__ cnt)
{
    __shared__ uint32_t Whi[2][64][36], Wlo[2][64][36];
    int bx = blockIdx.x;
    if (bx < W_BLK)     { dual_body(jw, bx, Whi[0], Wlo[0], Whi[1], Wlo[1]); return; }
    if (bx == W_BLK)    { dual_body(jg, 0,  Whi[0], Wlo[0], Whi[1], Wlo[1]); return; }
    if (bx == W_BLK+1)  { dual_body(jt, 0,  Whi[0], Wlo[0], Whi[1], Wlo[1]); return; }
    if (bx < PD_DEG) {
        int i = (bx - PD_PREP) * 256 + threadIdx.x;
        if (i < CC*CC) {
            g_WrS1[i] = Wr1[i] + Wr1[2*CC*CC+i] + Wr1[4*CC*CC+i] + Wr1[6*CC*CC+i];
            g_WrS2[i] = Wr2[i] + Wr2[2*CC*CC+i] + Wr2[4*CC*CC+i] + Wr2[6*CC*CC+i];
        }
        if (i < CC) {
            g_blS1[i] = bl1[i] + bl1[2*CC+i] + bl1[4*CC+i] + bl1[6*CC+i];
            g_blS2[i] = bl2[i] + bl2[2*CC+i] + bl2[4*CC+i] + bl2[6*CC+i];
        }
        return;
    }
    const int stride = PD_DEGBLK * 256;
    int base = (bx - PD_DEG) * 256 + threadIdx.x;
    for (int i = base; i < E_US; i += stride) {
        atomicAdd(cnt + CNT_U  + u2s[i], 1);
        atomicAdd(cnt + CNT_SU + u2s[E_US + i], 1);
    }
    for (int i = base; i < E_GS; i += stride) {
        atomicAdd(cnt + CNT_G  + g2s[i], 1);
        atomicAdd(cnt + CNT_SG + g2s[E_GS + i], 1);
    }
    for (int i = base; i < E_WS; i += stride) {
        atomicAdd(cnt + CNT_W  + w2s[i], 1);
        atomicAdd(cnt + CNT_SW + w2s[E_WS + i], 1);
    }
    for (int i = base; i < E_TS; i += stride) {
        atomicAdd(cnt + CNT_T  + t2s[i], 1);
        atomicAdd(cnt + CNT_ST + t2s[E_TS + i], 1);
    }
}

// ---------------- scans ----------------
__global__ void scan1(const int* __restrict__ cnt, int* __restrict__ csum) {
    __shared__ int sh[8];
    int c = blockIdx.x, t = threadIdx.x, base = c * CHUNK;
    int s = 0;
#pragma unroll
    for (int q = 0; q < 4; q++) {
        int idx = base + t*4 + q;
        if (idx < N_SCAN) s += cnt[idx];
    }
    for (int o = 16; o; o >>= 1) s += __shfl_down_sync(~0u, s, o);
    if ((t & 31) == 0) sh[t >> 5] = s;
    __syncthreads();
    if (t == 0) { int tot = 0; for (int w = 0; w < 8; w++) tot += sh[w]; csum[c] = tot; }
}

__global__ void scan23(const int* __restrict__ cnt, const int* __restrict__ csum,
                       int* __restrict__ off) {
    __shared__ int sh[8], sh2[8], basev;
    int c = blockIdx.x, t = threadIdx.x;
    int lane = t & 31, w = t >> 5;

    int p = 0;
    for (int i = t; i < c; i += 256) p += csum[i];
    for (int o = 16; o; o >>= 1) p += __shfl_down_sync(~0u, p, o);
    if (lane == 0) sh2[w] = p;
    __syncthreads();
    if (t == 0) { int a = 0; for (int i = 0; i < 8; i++) a += sh2[i]; basev = a; }
    __syncthreads();
    const int cbase = basev;

    int base = c * CHUNK;
    int v[4]; int s = 0;
#pragma unroll
    for (int q = 0; q < 4; q++) {
        int idx = base + t*4 + q;
        v[q] = (idx < N_SCAN) ? cnt[idx] : 0;
        s += v[q];
    }
    int incl = s;
    for (int o = 1; o < 32; o <<= 1) {
        int x = __shfl_up_sync(~0u, incl, o);
        if (lane >= o) incl += x;
    }
    if (lane == 31) sh[w] = incl;
    __syncthreads();
    if (t == 0) { int a = 0; for (int i = 0; i < 8; i++) { int x = sh[i]; sh[i] = a; a += x; } }
    __syncthreads();
    int excl = incl - s + sh[w] + cbase;
#pragma unroll
    for (int q = 0; q < 4; q++) {
        int idx = base + t*4 + q;
        if (idx < N_SCAN) off[idx] = excl;
        excl += v[q];
        if (idx == N_SCAN - 1) off[N_SCAN] = excl;
    }
}

// ---------------- p0 mega: big GEMMs + chains, fill_csr as 3rd slice ----------------
#define P0_GX 3907    // max(U_BLK, cdiv(E_US,256))

__global__ void __launch_bounds__(256) p0_mega(
    const P0Job j0, const P0Job j1,
    const int* __restrict__ u2s, const int* __restrict__ g2s,
    const int* __restrict__ w2s, const int* __restrict__ t2s,
    const int* __restrict__ off, int* __restrict__ cur, int* __restrict__ csr)
{
    if (blockIdx.y == 2) {
        int i = blockIdx.x * 256 + threadIdx.x;
        if (i < E_US) {
            int u = u2s[i], s = u2s[E_US + i];
            int n0 = CNT_SU + s;
            csr[off[n0] + atomicAdd(cur + n0, 1)] = u;
            int n1 = CNT_U + u;
            csr[off[n1] + atomicAdd(cur + n1, 1)] = s;
        }
        if (i < E_GS) {
            int gg = g2s[i], s = g2s[E_GS + i];
            int n = CNT_SG + s;
            csr[off[n] + atomicAdd(cur + n, 1)] = gg;
        }
        if (i < E_WS) {
            int ww = w2s[i], s = w2s[E_WS + i];
            int n = CNT_SW + s;
            csr[off[n] + atomicAdd(cur + n, 1)] = ww;
        }
        if (i < E_TS) {
            int tt = t2s[i], s = t2s[E_TS + i];
            int n = CNT_ST + s;
            csr[off[n] + atomicAdd(cur + n, 1)] = tt;
        }
        return;
    }
    const P0Job jb = blockIdx.y ? j1 : j0;
    const int m0 = blockIdx.x * 128;
    if (m0 >= jb.M) return;

    __shared__ uint32_t Whi[64][36], Wlo[64][36];
    const int tid = threadIdx.x, wid = tid >> 5, lane = tid & 31;
    const int g = lane >> 2, tg = lane & 3;

    float acc1[8][4];
#pragma unroll
    for (int j = 0; j < 8; j++) { acc1[j][0]=acc1[j][1]=acc1[j][2]=acc1[j][3]=0.f; }

    const int mtop = jb.M - 1;
    const int mr0 = m0 + wid * 16 + g;
    const float* A0 = jb.A + (size_t)min(mr0,     mtop) * FF;
    const float* A1 = jb.A + (size_t)min(mr0 + 8, mtop) * FF;

    for (int k0 = 0; k0 < FF; k0 += 64) {
        if (k0) __syncthreads();
        stage_w(jb.W, FF, k0, Whi, Wlo, tid);
        __syncthreads();
#pragma unroll
        for (int ks = 0; ks < 4; ks++) {
            uint32_t ah[4], al[4];
            load_afrag(A0, A1, k0 + ks*16 + 2*tg, 0, ah, al);
            mma_shared(acc1, ah, al, Whi, Wlo, ks, g, tg);
        }
    }

#pragma unroll
    for (int j = 0; j < 8; j++) {
        int n = j*8 + 2*tg;
        float b0 = jb.bias[n], b1 = jb.bias[n+1];
        acc1[j][0] += b0; acc1[j][1] += b1;
        acc1[j][2] += b0; acc1[j][3] += b1;
    }
    if (jb.xout) store_frag(acc1, nullptr, jb.xout, mr0, jb.M, tg);

    float a2a[8][4], a2b[8][4];
#pragma unroll
    for (int j = 0; j < 8; j++) {
        a2a[j][0]=a2a[j][1]=a2a[j][2]=a2a[j][3]=0.f;
        a2b[j][0]=a2b[j][1]=a2b[j][2]=a2b[j][3]=0.f;
    }
    chain_dual(acc1, jb.Wc0, jb.Wc1, a2a, a2b, g, tg);
    store_frag(a2a, jb.bc0, jb.oc0, mr0, jb.M, tg);
    store_frag_h(a2b, jb.oc1, mr0, jb.M, tg);
}

// ---------------- gather (+optional fused scatter blocks) ----------------
#define GATH_BLK 18750                 // (NS+NU)*32/256
#define SCAT_E   (E_GS + E_WS + E_TS)
#define SCAT_BLK ((SCAT_E * 8 + 255) / 256)

__global__ void __launch_bounds__(256) gather_scatter(
    const __half* __restrict__ tU, const __half* __restrict__ tS,
    const __half* __restrict__ tG, const __half* __restrict__ tW, const __half* __restrict__ tT,
    float* __restrict__ outS, float* __restrict__ outU,
    const int* __restrict__ off, const int* __restrict__ csr,
    const ScatJob s0, const ScatJob s1, const ScatJob s2)
{
    int bx = blockIdx.x;
    if (bx >= GATH_BLK) {
        int gid = (bx - GATH_BLK) * 256 + threadIdx.x;
        int ge = gid >> 3;
        if (ge >= SCAT_E) return;
        int part = gid & 7;
        const ScatJob jb = (ge < E_GS) ? s0 : (ge < E_GS + E_WS ? s1 : s2);
        int e = (ge < E_GS) ? ge : (ge < E_GS + E_WS ? ge - E_GS : ge - E_GS - E_WS);
        int s = jb.src[e], d = jb.dst[e];
        const float4* xp = (const float4*)(jb.x + (size_t)s * CC);
        float4*       op = (float4*)(jb.out + (size_t)d * CC);
        atomicAdd(op + part,     xp[part]);
        atomicAdd(op + part + 8, xp[part + 8]);
        return;
    }
    int gw = (bx * 256 + threadIdx.x) >> 5;
    int lane = threadIdx.x & 31;
    int hf = lane >> 4;
    int col = (lane & 15) * 4;
    float4 s = make_float4(0.f, 0.f, 0.f, 0.f);
    float* o;

    if (gw < NS) {
        const int d = gw;
        const int node[4] = { CNT_SU + d, CNT_SG + d, CNT_SW + d, CNT_ST + d };
        const __half* buf[4] = { tU, tG, tW, tT };
#pragma unroll
        for (int f = 0; f < 4; f++) {
            int b = off[node[f]], e = off[node[f] + 1];
            float4 fa = make_float4(0.f, 0.f, 0.f, 0.f);
#pragma unroll 2
            for (int i = b + hf; i < e; i += 2) {
                int src = csr[i];
                uint2 raw = *(const uint2*)(buf[f] + (size_t)src * CC + col);
                float2 v0 = __half22float2(*(__half2*)&raw.x);
                float2 v1 = __half22float2(*(__half2*)&raw.y);
                fa.x += v0.x; fa.y += v0.y; fa.z += v1.x; fa.w += v1.y;
            }
            float inv = 1.f / fmaxf((float)(e - b), 1.f);
            s.x += fa.x * inv; s.y += fa.y * inv; s.z += fa.z * inv; s.w += fa.w * inv;
        }
        o = outS + (size_t)d * CC + col;
    } else if (gw < NS + NU) {
        const int d = gw - NS;
        int b = off[CNT_U + d], e = off[CNT_U + d + 1];
        float4 fa = make_float4(0.f, 0.f, 0.f, 0.f);
#pragma unroll 2
        for (int i = b + hf; i < e; i += 2) {
            int src = csr[i];
            uint2 raw = *(const uint2*)(tS + (size_t)src * CC + col);
            float2 v0 = __half22float2(*(__half2*)&raw.x);
            float2 v1 = __half22float2(*(__half2*)&raw.y);
            fa.x += v0.x; fa.y += v0.y; fa.z += v1.x; fa.w += v1.y;
        }
        float inv = 1.f / fmaxf((float)(e - b), 1.f);
        s.x = fa.x * inv; s.y = fa.y * inv; s.z = fa.z * inv; s.w = fa.w * inv;
        o = outU + (size_t)d * CC + col;
    } else return;

    s.x += __shfl_xor_sync(~0u, s.x, 16);
    s.y += __shfl_xor_sync(~0u, s.y, 16);
    s.z += __shfl_xor_sync(~0u, s.z, 16);
    s.w += __shfl_xor_sync(~0u, s.w, 16);
    if (hf == 0) {
        float4 c = *(const float4*)o;
        *(float4*)o = make_float4(c.x + s.x, c.y + s.y, c.z + s.z, c.w + s.w);
    }
}

// ---------------- wave2: layer-2 duals + fused layer1-finalize chains ----------------
#define W2_B1 (U_BLK)
#define W2_B2 (U_BLK + S_BLK)
#define W2_B3 (U_BLK + S_BLK + W_BLK)
#define W2_TOT (U_BLK + S_BLK + W_BLK + 2)

__global__ void __launch_bounds__(256) wave2(
    const DualJob d0, const DualJob d1,
    const FBJob f0, const FBJob f1, const FBJob f2)
{
    __shared__ uint32_t Whi[2][64][36], Wlo[2][64][36];
    int bx = blockIdx.x;
    if (bx < W2_B1)      { dual_body(d0, bx,          Whi[0], Wlo[0], Whi[1], Wlo[1]); return; }
    if (bx < W2_B2)      { dual_body(d1, bx - W2_B1,  Whi[0], Wlo[0], Whi[1], Wlo[1]); return; }
    if (bx < W2_B3)      { fb_body(f0, bx - W2_B2,    Whi[0], Wlo[0]); return; }
    if (bx == W2_B3)     { fb_body(f1, 0,             Whi[0], Wlo[0]); return; }
    fb_body(f2, 0, Whi[0], Wlo[0]);
}

// ---------------- classifier ----------------
__global__ void dot_score(const float* __restrict__ xu, const float* __restrict__ xs,
                          const int* __restrict__ ui, const int* __restrict__ si,
                          float* __restrict__ out, int E) {
    int gid = blockIdx.x * blockDim.x + threadIdx.x;
    int e = gid >> 4;
    int j = (gid & 15) << 2;
    int ec = (e < E) ? e : (E - 1);
    float4 a = *(const float4*)(xu + (size_t)ui[ec] * CC + j);
    float4 b = *(const float4*)(xs + (size_t)si[ec] * CC + j);
    float d = a.x*b.x + a.y*b.y + a.z*b.z + a.w*b.w;
    d += __shfl_xor_sync(0xffffffffu, d, 1);
    d += __shfl_xor_sync(0xffffffffu, d, 2);
    d += __shfl_xor_sync(0xffffffffu, d, 4);
    d += __shfl_xor_sync(0xffffffffu, d, 8);
    if ((gid & 15) == 0 && e < E) out[e] = d;
}

static inline int cdiv(int a, int b) { return (a + b - 1) / b; }

extern "C" void kernel_launch(void* const* d_in, const int* in_sizes, int n_in,
                              void* d_out, int out_size)
{
    const float* reviews  = (const float*)d_in[0];
    const float* overview = (const float*)d_in[1];
    const float* g_emb    = (const float*)d_in[2];
    const float* w_emb    = (const float*)d_in[3];
    const float* t_emb    = (const float*)d_in[4];
    const float* Wu  = (const float*)d_in[5];
    const float* bu  = (const float*)d_in[6];
    const float* Wsw = (const float*)d_in[7];
    const float* bs  = (const float*)d_in[8];
    const float* Wl1 = (const float*)d_in[9];
    const float* bl1 = (const float*)d_in[10];
    const float* Wr1 = (const float*)d_in[11];
    const float* Wl2 = (const float*)d_in[12];
    const float* bl2 = (const float*)d_in[13];
    const float* Wr2 = (const float*)d_in[14];
    const int* e_u2s = (const int*)d_in[15];
    const int* e_g2s = (const int*)d_in[16];
    const int* e_w2s = (const int*)d_in[17];
    const int* e_t2s = (const int*)d_in[18];
    const int* eli   = (const int*)d_in[19];
    float* out = (float*)d_out;

    int *cnt,*off,*csum,*csr;
    float *agg,*xs,*yu,*ys,*xu2,*xs2,*xwp,*xgp,*xtp;
    __half *tU,*tS,*tG,*tW,*tT,*tU2,*tS2,*tG2,*tW2,*tT2;
    float *WrS1,*blS1,*WrS2,*blS2;
    cudaGetSymbolAddress((void**)&cnt,  g_cnt);
    cudaGetSymbolAddress((void**)&off,  g_off);
    cudaGetSymbolAddress((void**)&csum, g_csum);
    cudaGetSymbolAddress((void**)&csr,  g_csr);
    cudaGetSymbolAddress((void**)&agg,  g_agg);
    cudaGetSymbolAddress((void**)&xs,   g_xs);
    cudaGetSymbolAddress((void**)&yu,   g_yu);
    cudaGetSymbolAddress((void**)&ys,   g_ys);
    cudaGetSymbolAddress((void**)&xu2,  g_xu2);
    cudaGetSymbolAddress((void**)&xs2,  g_xs2);
    cudaGetSymbolAddress((void**)&tU,   g_tU);
    cudaGetSymbolAddress((void**)&tS,   g_tS);
    cudaGetSymbolAddress((void**)&tG,   g_tG);
    cudaGetSymbolAddress((void**)&tW,   g_tW);
    cudaGetSymbolAddress((void**)&tT,   g_tT);
    cudaGetSymbolAddress((void**)&tU2,  g_tU2);
    cudaGetSymbolAddress((void**)&tS2,  g_tS2);
    cudaGetSymbolAddress((void**)&tG2,  g_tG2);
    cudaGetSymbolAddress((void**)&tW2,  g_tW2);
    cudaGetSymbolAddress((void**)&tT2,  g_tT2);
    cudaGetSymbolAddress((void**)&xwp,  g_xwp);
    cudaGetSymbolAddress((void**)&xgp,  g_xgp);
    cudaGetSymbolAddress((void**)&xtp,  g_xtp);
    cudaGetSymbolAddress((void**)&WrS1, g_WrS1);
    cudaGetSymbolAddress((void**)&blS1, g_blS1);
    cudaGetSymbolAddress((void**)&WrS2, g_WrS2);
    cudaGetSymbolAddress((void**)&blS2, g_blS2);

    int* cur = cnt + CNT_TOT;
    const int W44 = CC*CC;

    // ---- init ----
    cudaMemsetAsync(cnt, 0, (CNT_TOT + N_SCAN) * sizeof(int));
    cudaMemsetAsync(agg, 0, AGG_TOT * sizeof(float));

    // ---- launch 1: small duals + weight prep + degree count ----
    {
        DualJob jw = { w_emb, Wl1 + 4*W44, tW, Wr1 + 5*W44, bl1 + 5*CC, xwp, NW, 0 };
        DualJob jg = { g_emb, Wl1 + 2*W44, tG, Wr1 + 3*W44, bl1 + 3*CC, xgp, NG, 0 };
        DualJob jt = { t_emb, Wl1 + 6*W44, tT, Wr1 + 7*W44, bl1 + 7*CC, xtp, NT, 0 };
        prep_deg_duals<<<PD_TOT, 256>>>(jw, jg, jt, Wr1, bl1, Wr2, bl2,
                                        e_u2s, e_g2s, e_w2s, e_t2s, cnt);
    }

    // ---- scans ----
    scan1<<<NCHUNK, 256>>>(cnt, csum);
    scan23<<<NCHUNK, 256>>>(cnt, csum, off);

    // ---- p0: big transforms + chained layer-1 pre-terms; fill_csr rides as slice 2 ----
    {
        P0Job ju = { reviews,  Wu,  bu, nullptr,
                     Wr1 + 1*W44, bl1 + 1*CC, yu,
                     Wl1 + 0*W44, tU, NU };
        P0Job js = { overview, Wsw, bs, xs,
                     WrS1, blS1, ys,
                     Wl1 + 1*W44, tS, NS };
        p0_mega<<<dim3(P0_GX, 3), 256>>>(ju, js, e_u2s, e_g2s, e_w2s, e_t2s, off, cur, csr);
    }

    // ---- gather 1 + s->g/w/t scatter (fused) ----
    {
        ScatJob s0 = { xs, e_g2s + E_GS, e_g2s, agg + AGG_G };
        ScatJob s1 = { xs, e_w2s + E_WS, e_w2s, agg + AGG_W };
        ScatJob s2 = { xs, e_t2s + E_TS, e_t2s, agg + AGG_T };
        gather_scatter<<<GATH_BLK + SCAT_BLK, 256>>>(tU, tS, tG, tW, tT, ys, yu,
                                                     off, csr, s0, s1, s2);
    }

    // ---- wave2 ----
    {
        DualJob d0 = { yu, Wl2 + 0*W44, tU2, Wr2 + 1*W44, bl2 + 1*CC, xu2, NU, 1 };
        DualJob d1 = { ys, Wl2 + 1*W44, tS2, WrS2,        blS2,       xs2, NS, 1 };
        FBJob f0 = { agg + AGG_W, Wl1 + 5*W44, xwp, cnt + CNT_W, Wl2 + 4*W44, tW2, NW };
        FBJob f1 = { agg + AGG_G, Wl1 + 3*W44, xgp, cnt + CNT_G, Wl2 + 2*W44, tG2, NG };
        FBJob f2 = { agg + AGG_T, Wl1 + 7*W44, xtp, cnt + CNT_T, Wl2 + 6*W44, tT2, NT };
        wave2<<<W2_TOT, 256>>>(d0, d1, f0, f1, f2);
    }

    // ---- gather 2 (no scatter blocks) ----
    {
        ScatJob sd = { nullptr, nullptr, nullptr, nullptr };
        gather_scatter<<<GATH_BLK, 256>>>(tU2, tS2, tG2, tW2, tT2, xs2, xu2,
                                          off, csr, sd, sd, sd);
    }

    // ---- classifier ----
    dot_score<<<E_LI*16/256, 256>>>(xu2, xs2, eli, eli + E_LI, out, E_LI);
}